// round 1
// baseline (speedup 1.0000x reference)
#include <cuda_runtime.h>

#define NB 16
#define NL 2048
#define NF 46
#define D_MODEL 256
#define D_INNER 512
#define D_STATE 64
#define NHEADS 8
#define HEADDIM 64
#define CONV_DIM 640
#define D_IN_PROJ 1160
#define N_LAYERS 4
#define BL (NB*NL)

// ---------------- scratch (static device globals; no runtime allocation) ----
__device__ float g_h[(size_t)BL * D_MODEL];      // residual stream
__device__ float g_zx[(size_t)BL * D_IN_PROJ];   // in_proj output
__device__ float g_xc[(size_t)BL * CONV_DIM];    // conv+silu output
__device__ float g_dt[(size_t)BL * NHEADS];      // softplus(dt)
__device__ float g_y[(size_t)BL * D_INNER];      // scan output / gated-norm
__device__ float g_part[NB * 32 * D_MODEL];      // LN partial sums

// ---------------- packed f32x2 helpers (sm_103a) ----------------------------
__device__ __forceinline__ unsigned long long pk2(float x, float y) {
    unsigned long long r;
    asm("mov.b64 %0, {%1, %2};" : "=l"(r) : "f"(x), "f"(y));
    return r;
}
__device__ __forceinline__ void upk2(unsigned long long v, float &x, float &y) {
    asm("mov.b64 {%0, %1}, %2;" : "=f"(x), "=f"(y) : "l"(v));
}
__device__ __forceinline__ unsigned long long fma2(unsigned long long a,
                                                   unsigned long long b,
                                                   unsigned long long c) {
    unsigned long long d;
    asm("fma.rn.f32x2 %0, %1, %2, %3;" : "=l"(d) : "l"(a), "l"(b), "l"(c));
    return d;
}
__device__ __forceinline__ unsigned long long mul2(unsigned long long a,
                                                   unsigned long long b) {
    unsigned long long d;
    asm("mul.rn.f32x2 %0, %1, %2;" : "=l"(d) : "l"(a), "l"(b));
    return d;
}

// ---------------- generic tiled SGEMM: C[M,N] (+)= A[M,K] @ B[K,N] (+bias) ---
// BM=64, BN=64, BK=16, 128 threads, 4x8 micro-tile per thread.
// M must be a multiple of 64 (true for all call sites: M = 32768).
__global__ void __launch_bounds__(128) sgemm_k(
    const float* __restrict__ A, const float* __restrict__ B,
    const float* __restrict__ bias, float* __restrict__ C,
    int M, int N, int K, int acc_flag)
{
    __shared__ __align__(16) float As[16][68];
    __shared__ __align__(16) float Bs[16][64];
    const int bm = blockIdx.y * 64;
    const int bn = blockIdx.x * 64;
    const int tid = threadIdx.x;
    const int tx = tid & 7;          // 0..7   (col group of 8)
    const int ty = tid >> 3;         // 0..15  (row group of 4)
    const int aRow = tid >> 4;       // 0..7
    const int aCol = tid & 15;       // 0..15
    const int bRow = tid >> 6;       // 0..1
    const int bCol = tid & 63;       // 0..63

    float acc[4][8];
#pragma unroll
    for (int i = 0; i < 4; i++)
#pragma unroll
        for (int j = 0; j < 8; j++) acc[i][j] = 0.f;

    for (int k0 = 0; k0 < K; k0 += 16) {
#pragma unroll
        for (int i = 0; i < 8; i++) {
            int m = bm + aRow + 8 * i;
            int k = k0 + aCol;
            As[aCol][aRow + 8 * i] = (k < K) ? A[(size_t)m * K + k] : 0.f;
        }
#pragma unroll
        for (int i = 0; i < 8; i++) {
            int k = k0 + bRow + 2 * i;
            int n = bn + bCol;
            Bs[bRow + 2 * i][bCol] = (k < K && n < N) ? B[(size_t)k * N + n] : 0.f;
        }
        __syncthreads();
#pragma unroll
        for (int k = 0; k < 16; k++) {
            float4 a4  = *(const float4*)&As[k][ty * 4];
            float4 b4a = *(const float4*)&Bs[k][tx * 8];
            float4 b4b = *(const float4*)&Bs[k][tx * 8 + 4];
            float a[4]  = {a4.x, a4.y, a4.z, a4.w};
            float bb[8] = {b4a.x, b4a.y, b4a.z, b4a.w, b4b.x, b4b.y, b4b.z, b4b.w};
#pragma unroll
            for (int i = 0; i < 4; i++)
#pragma unroll
                for (int j = 0; j < 8; j++)
                    acc[i][j] = fmaf(a[i], bb[j], acc[i][j]);
        }
        __syncthreads();
    }
#pragma unroll
    for (int i = 0; i < 4; i++) {
        int m = bm + ty * 4 + i;
#pragma unroll
        for (int j = 0; j < 8; j++) {
            int n = bn + tx * 8 + j;
            if (n < N) {
                float v = acc[i][j];
                if (bias) v += bias[n];
                size_t off = (size_t)m * N + n;
                if (acc_flag) v += C[off];
                C[off] = v;
            }
        }
    }
}

// ---------------- depthwise causal conv (k=4) + bias + silu -----------------
__global__ void conv_silu_k(const float* __restrict__ cw, const float* __restrict__ cb)
{
    int idx = blockIdx.x * 256 + threadIdx.x;
    if (idx >= BL * CONV_DIM) return;
    int c  = idx % CONV_DIM;
    int bl = idx / CONV_DIM;
    int l  = bl % NL;
    float s = cb[c];
#pragma unroll
    for (int k = 0; k < 4; k++) {
        int lk = l - 3 + k;
        if (lk >= 0)
            s = fmaf(g_zx[(size_t)(bl - 3 + k) * D_IN_PROJ + 512 + c], cw[c * 4 + k], s);
    }
    s = s / (1.f + __expf(-s));   // silu
    g_xc[idx] = s;
}

// ---------------- dt = softplus(raw + bias) ---------------------------------
__global__ void dt_k(const float* __restrict__ dtb)
{
    int idx = blockIdx.x * 256 + threadIdx.x;
    if (idx >= BL * NHEADS) return;
    int h  = idx & 7;
    int bl = idx >> 3;
    float v = g_zx[(size_t)bl * D_IN_PROJ + 1152 + h] + dtb[h];
    g_dt[idx] = (v > 20.f) ? v : log1pf(expf(v));
}

// ---------------- selective scan: one CTA per (b, head) ---------------------
// 128 threads. Thread = (p, half): p = warp*16 + (lane&15) in [0,64),
// half = lane>>4 selects n in [32*half, 32*half+32). State is 16 packed f32x2
// registers per thread. y reduced across halves with one shfl.xor(16).
__global__ void __launch_bounds__(128) scan_k(const float* __restrict__ Alog,
                                              const float* __restrict__ Dp)
{
    int bh = blockIdx.x;
    int b = bh >> 3, h = bh & 7;
    int lane = threadIdx.x & 31;
    int w = threadIdx.x >> 5;
    int p = w * 16 + (lane & 15);
    int half = (lane >> 4) & 1;

    float Ah = -__expf(Alog[h]);
    float Dh = Dp[h];

    unsigned long long st[16];
#pragma unroll
    for (int i = 0; i < 16; i++) st[i] = 0ULL;

    const float* xcb = g_xc + (size_t)b * NL * CONV_DIM;
    const float* dts = g_dt + (size_t)b * NL * NHEADS + h;
    float* yb = g_y + (size_t)b * NL * D_INNER + h * HEADDIM + p;

    for (int l = 0; l < NL; l++) {
        const float* row = xcb + (size_t)l * CONV_DIM;
        float dt = dts[(size_t)l * NHEADS];
        float dA = __expf(dt * Ah);
        float xv = row[h * HEADDIM + p];
        float dtx = dt * xv;
        const float4* B4 = (const float4*)(row + 512 + 32 * half);
        const float4* C4 = (const float4*)(row + 576 + 32 * half);
        unsigned long long dA2 = pk2(dA, dA);
        unsigned long long dx2 = pk2(dtx, dtx);
        unsigned long long ya = 0ULL;
#pragma unroll
        for (int j = 0; j < 8; j++) {
            float4 Bv = B4[j];
            float4 Cv = C4[j];
            unsigned long long b0 = pk2(Bv.x, Bv.y);
            unsigned long long b1 = pk2(Bv.z, Bv.w);
            unsigned long long c0 = pk2(Cv.x, Cv.y);
            unsigned long long c1 = pk2(Cv.z, Cv.w);
            st[2 * j]     = fma2(st[2 * j],     dA2, mul2(dx2, b0));
            ya            = fma2(st[2 * j],     c0, ya);
            st[2 * j + 1] = fma2(st[2 * j + 1], dA2, mul2(dx2, b1));
            ya            = fma2(st[2 * j + 1], c1, ya);
        }
        float y0, y1;
        upk2(ya, y0, y1);
        float ys = y0 + y1;
        ys += __shfl_xor_sync(0xffffffffu, ys, 16);
        if (!(lane & 16))
            yb[(size_t)l * D_INNER] = fmaf(Dh, xv, ys);
    }
}

// ---------------- y = rmsnorm(y * silu(z)) * rms_w, one CTA per (b,l) row ---
__global__ void __launch_bounds__(128) gate_rms_k(const float* __restrict__ rmsw)
{
    int row = blockIdx.x;
    int t = threadIdx.x;
    const float4* y4 = (const float4*)(g_y  + (size_t)row * D_INNER);
    const float4* z4 = (const float4*)(g_zx + (size_t)row * D_IN_PROJ);
    float4 yv = y4[t];
    float4 zv = z4[t];
    float4 g;
    g.x = yv.x * (zv.x / (1.f + __expf(-zv.x)));
    g.y = yv.y * (zv.y / (1.f + __expf(-zv.y)));
    g.z = yv.z * (zv.z / (1.f + __expf(-zv.z)));
    g.w = yv.w * (zv.w / (1.f + __expf(-zv.w)));
    float ss = g.x * g.x + g.y * g.y + g.z * g.z + g.w * g.w;
#pragma unroll
    for (int o = 16; o > 0; o >>= 1) ss += __shfl_xor_sync(0xffffffffu, ss, o);
    __shared__ float sb[4];
    if ((t & 31) == 0) sb[t >> 5] = ss;
    __syncthreads();
    float tot = sb[0] + sb[1] + sb[2] + sb[3];
    float sc = rsqrtf(tot * (1.f / 512.f) + 1e-5f);
    const float4* w4 = (const float4*)rmsw;
    float4 wv = w4[t];
    float4 o;
    o.x = g.x * sc * wv.x;
    o.y = g.y * sc * wv.y;
    o.z = g.z * sc * wv.z;
    o.w = g.w * sc * wv.w;
    ((float4*)(g_y + (size_t)row * D_INNER))[t] = o;
}

// ---------------- final LayerNorm (per row) + partial mean over l -----------
// grid (16, 32): block b, l-chunk of 64. Accumulates un-affined normalized
// values (affine folded into final_k since it is linear over the l-mean).
__global__ void __launch_bounds__(256) ln_part_k()
{
    __shared__ float sb[8];
    int b = blockIdx.x;
    int chunk = blockIdx.y;
    int c = threadIdx.x;
    int lane = c & 31, wid = c >> 5;
    float acc = 0.f;
    for (int i = 0; i < 64; i++) {
        int l = chunk * 64 + i;
        float v = g_h[((size_t)(b * NL + l)) * D_MODEL + c];
        float s = v;
#pragma unroll
        for (int o = 16; o > 0; o >>= 1) s += __shfl_xor_sync(0xffffffffu, s, o);
        if (lane == 0) sb[wid] = s;
        __syncthreads();
        float tot = sb[0] + sb[1] + sb[2] + sb[3] + sb[4] + sb[5] + sb[6] + sb[7];
        __syncthreads();
        float mu = tot * (1.f / 256.f);
        float d = v - mu;
        float s2 = d * d;
#pragma unroll
        for (int o = 16; o > 0; o >>= 1) s2 += __shfl_xor_sync(0xffffffffu, s2, o);
        if (lane == 0) sb[wid] = s2;
        __syncthreads();
        float var = (sb[0] + sb[1] + sb[2] + sb[3] + sb[4] + sb[5] + sb[6] + sb[7]) * (1.f / 256.f);
        __syncthreads();
        acc += d * rsqrtf(var + 1e-5f);
    }
    g_part[((size_t)(b * 32 + chunk)) * D_MODEL + c] = acc;
}

// ---------------- reduce partials, apply LN affine, compute heads -----------
__global__ void __launch_bounds__(256) final_k(
    const float* __restrict__ lnw, const float* __restrict__ lnb,
    const float* __restrict__ dirw, const float* __restrict__ dirb,
    const float* __restrict__ regw, const float* __restrict__ regb,
    float* __restrict__ out)
{
    __shared__ float hb[NB * D_MODEL];
    int t = threadIdx.x;
#pragma unroll
    for (int i = 0; i < (NB * D_MODEL) / 256; i++) {
        int idx = t + i * 256;
        int c = idx & 255;
        int bb = idx >> 8;
        float s = 0.f;
#pragma unroll
        for (int j = 0; j < 32; j++)
            s += g_part[((size_t)(bb * 32 + j)) * D_MODEL + c];
        hb[idx] = s * (1.f / 2048.f) * lnw[c] + lnb[c];
    }
    __syncthreads();
    if (t < NB) {
        float s = dirb[0];
        for (int c = 0; c < D_MODEL; c++) s += hb[t * D_MODEL + c] * dirw[c];
        out[t] = s;                     // dir_logits, flattened first
    } else if (t < NB + NB * 3) {
        int q = t - NB;
        int bb = q / 3, j = q % 3;
        float s = regb[j];
        for (int c = 0; c < D_MODEL; c++) s += hb[bb * D_MODEL + c] * regw[c * 3 + j];
        out[NB + q] = s;                // reg_out, flattened second
    }
}

// ---------------- launch ----------------------------------------------------
extern "C" void kernel_launch(void* const* d_in, const int* in_sizes, int n_in,
                              void* d_out, int out_size)
{
    const float* x    = (const float*)d_in[0];
    const float* inpw = (const float*)d_in[1];
    const float* inpb = (const float*)d_in[2];
    const float* ipw  = (const float*)d_in[3];
    const float* cw   = (const float*)d_in[4];
    const float* cb   = (const float*)d_in[5];
    const float* dtb  = (const float*)d_in[6];
    const float* alog = (const float*)d_in[7];
    const float* Dp   = (const float*)d_in[8];
    const float* rmsw = (const float*)d_in[9];
    const float* opw  = (const float*)d_in[10];
    const float* lnw  = (const float*)d_in[11];
    const float* lnb  = (const float*)d_in[12];
    const float* dirw = (const float*)d_in[13];
    const float* dirb = (const float*)d_in[14];
    const float* regw = (const float*)d_in[15];
    const float* regb = (const float*)d_in[16];
    float* out = (float*)d_out;

    void *ph_, *pzx_, *py_;
    cudaGetSymbolAddress(&ph_,  g_h);
    cudaGetSymbolAddress(&pzx_, g_zx);
    cudaGetSymbolAddress(&py_,  g_y);
    float* ph  = (float*)ph_;
    float* pzx = (float*)pzx_;
    float* py  = (float*)py_;

    // h = x @ inp_w + inp_b            [32768 x 256, K=46]
    sgemm_k<<<dim3(D_MODEL / 64, BL / 64), 128>>>(x, inpw, inpb, ph, BL, D_MODEL, NF, 0);

    for (int i = 0; i < N_LAYERS; i++) {
        // zxbcdt = h @ in_proj_w       [32768 x 1160, K=256]
        sgemm_k<<<dim3((D_IN_PROJ + 63) / 64, BL / 64), 128>>>(
            ph, ipw + (size_t)i * D_MODEL * D_IN_PROJ, nullptr, pzx,
            BL, D_IN_PROJ, D_MODEL, 0);
        // conv + silu over xBC
        conv_silu_k<<<(BL * CONV_DIM + 255) / 256, 256>>>(
            cw + (size_t)i * CONV_DIM * 4, cb + (size_t)i * CONV_DIM);
        // dt = softplus(dt_raw + dt_bias)
        dt_k<<<(BL * NHEADS + 255) / 256, 256>>>(dtb + i * NHEADS);
        // selective scan (+ D*x skip)
        scan_k<<<NB * NHEADS, 128>>>(alog + i * NHEADS, Dp + i * NHEADS);
        // y = rmsnorm(y * silu(z)) * rms_w
        gate_rms_k<<<BL, 128>>>(rmsw + (size_t)i * D_INNER);
        // h += y @ out_proj_w          [32768 x 256, K=512], accumulate
        sgemm_k<<<dim3(D_MODEL / 64, BL / 64), 128>>>(
            py, opw + (size_t)i * D_INNER * D_MODEL, nullptr, ph,
            BL, D_MODEL, D_INNER, 1);
    }

    ln_part_k<<<dim3(NB, 32), 256>>>();
    final_k<<<1, 256>>>(lnw, lnb, dirw, dirb, regw, regb, out);
}

// round 2
// speedup vs baseline: 1.2349x; 1.2349x over previous
#include <cuda_runtime.h>
#include <cstdint>

#define NB 16
#define NL 2048
#define NF 46
#define D_MODEL 256
#define D_INNER 512
#define D_STATE 64
#define NHEADS 8
#define HEADDIM 64
#define CONV_DIM 640
#define D_IN_PROJ 1160
#define N_LAYERS 4
#define BL (NB*NL)

// ---------------- scratch (static device globals; no runtime allocation) ----
__device__ float g_h[(size_t)BL * D_MODEL];      // residual stream
__device__ float g_zx[(size_t)BL * D_IN_PROJ];   // in_proj output
__device__ float g_xc[(size_t)BL * CONV_DIM];    // conv+silu output
__device__ float g_dt[(size_t)BL * NHEADS];      // softplus(dt)
__device__ float g_y[(size_t)BL * D_INNER];      // scan output / gated-norm
__device__ float g_part[NB * 32 * D_MODEL];      // LN partial sums

// ---------------- packed f32x2 helpers (sm_103a) ----------------------------
__device__ __forceinline__ unsigned long long pk2(float x, float y) {
    unsigned long long r;
    asm("mov.b64 %0, {%1, %2};" : "=l"(r) : "f"(x), "f"(y));
    return r;
}
__device__ __forceinline__ void upk2(unsigned long long v, float &x, float &y) {
    asm("mov.b64 {%0, %1}, %2;" : "=f"(x), "=f"(y) : "l"(v));
}
__device__ __forceinline__ unsigned long long fma2(unsigned long long a,
                                                   unsigned long long b,
                                                   unsigned long long c) {
    unsigned long long d;
    asm("fma.rn.f32x2 %0, %1, %2, %3;" : "=l"(d) : "l"(a), "l"(b), "l"(c));
    return d;
}
__device__ __forceinline__ unsigned long long mul2(unsigned long long a,
                                                   unsigned long long b) {
    unsigned long long d;
    asm("mul.rn.f32x2 %0, %1, %2;" : "=l"(d) : "l"(a), "l"(b));
    return d;
}

// ---------------- tf32 / cp.async helpers ------------------------------------
__device__ __forceinline__ uint32_t to_tf32(float x) {
    uint32_t r;
    asm("cvt.rna.tf32.f32 %0, %1;" : "=r"(r) : "f"(x));
    return r;
}
__device__ __forceinline__ void cpa16(void* dst, const void* src) {
    uint32_t d = (uint32_t)__cvta_generic_to_shared(dst);
    asm volatile("cp.async.cg.shared.global [%0], [%1], 16;" :: "r"(d), "l"(src));
}
__device__ __forceinline__ void cpa16z(void* dst, const void* src, int bytes) {
    uint32_t d = (uint32_t)__cvta_generic_to_shared(dst);
    asm volatile("cp.async.cg.shared.global [%0], [%1], 16, %2;"
                 :: "r"(d), "l"(src), "r"(bytes));
}
__device__ __forceinline__ void cpa_commit() { asm volatile("cp.async.commit_group;"); }
__device__ __forceinline__ void cpa_wait0()  { asm volatile("cp.async.wait_group 0;"); }

__device__ __forceinline__ void mma_tf32(float c[4], const uint32_t a[4], const uint32_t b[2]) {
    asm volatile(
        "mma.sync.aligned.m16n8k8.row.col.f32.tf32.tf32.f32 "
        "{%0,%1,%2,%3}, {%4,%5,%6,%7}, {%8,%9}, {%0,%1,%2,%3};"
        : "+f"(c[0]), "+f"(c[1]), "+f"(c[2]), "+f"(c[3])
        : "r"(a[0]), "r"(a[1]), "r"(a[2]), "r"(a[3]), "r"(b[0]), "r"(b[1]));
}

// ---------------- tf32 tensor-core GEMM: C[M,N] (+)= A[M,K] @ B[K,N] --------
// BM=128, BN=64, BK=16, 256 threads (4x2 warps, 32x32 warp tile),
// double-buffered cp.async pipeline. K % 16 == 0, M % 128 == 0 required.
__global__ void __launch_bounds__(256) tf32gemm_k(
    const float* __restrict__ A, const float* __restrict__ B,
    float* __restrict__ C, int M, int N, int K, int acc_flag)
{
    __shared__ __align__(16) float As[2][128][20];   // [m][k], stride 20 -> conflict-free frags
    __shared__ __align__(16) float Bs[2][16][72];    // [k][n], stride 72 -> conflict-free frags

    const int tid  = threadIdx.x;
    const int bm   = blockIdx.y * 128;
    const int bn   = blockIdx.x * 64;
    const int warp = tid >> 5, lane = tid & 31;
    const int wm   = (warp >> 1) * 32;   // warp row offset in tile
    const int wn   = (warp & 1) * 32;    // warp col offset in tile
    const int g    = lane >> 2;          // 0..7
    const int tg   = lane & 3;           // 0..3

    float acc[2][4][4];
#pragma unroll
    for (int mt = 0; mt < 2; mt++)
#pragma unroll
        for (int nt = 0; nt < 4; nt++)
#pragma unroll
            for (int i = 0; i < 4; i++) acc[mt][nt][i] = 0.f;

    const int KT = K >> 4;

    // A-copy mapping: 512 float4 per stage, 2 per thread
    const int a_m0 = (tid * 2) >> 2;          // row of first float4
    const int a_k0 = ((tid * 2) & 3) * 4;     // k offset of first float4 (second is +4 idx -> same row, +? )
    // B-copy mapping: 256 float4 per stage, 1 per thread
    const int b_k  = tid >> 4;
    const int b_nq = (tid & 15) * 4;

    // stage loader
    auto load_stage = [&](int s, int k0) {
#pragma unroll
        for (int i = 0; i < 2; i++) {
            int idx = tid * 2 + i;
            int m = idx >> 2, kq = (idx & 3) * 4;
            cpa16(&As[s][m][kq], A + (size_t)(bm + m) * K + k0 + kq);
        }
        {
            int n = bn + b_nq;
            int nc = n < N - 4 ? n : N - 4;
            int bytes = (n < N) ? ((N - n) * 4 < 16 ? (N - n) * 4 : 16) : 0;
            cpa16z(&Bs[s][b_k][b_nq], B + (size_t)(k0 + b_k) * N + nc, bytes);
        }
        cpa_commit();
    };
    (void)a_m0; (void)a_k0;

    load_stage(0, 0);

    for (int kt = 0; kt < KT; kt++) {
        cpa_wait0();
        __syncthreads();
        if (kt + 1 < KT) load_stage((kt + 1) & 1, (kt + 1) * 16);
        const int s = kt & 1;
#pragma unroll
        for (int ks = 0; ks < 2; ks++) {
            uint32_t af[2][4];
#pragma unroll
            for (int mt = 0; mt < 2; mt++) {
                int r = wm + mt * 16 + g;
                int c = ks * 8 + tg;
                af[mt][0] = to_tf32(As[s][r][c]);
                af[mt][1] = to_tf32(As[s][r + 8][c]);
                af[mt][2] = to_tf32(As[s][r][c + 4]);
                af[mt][3] = to_tf32(As[s][r + 8][c + 4]);
            }
            uint32_t bf[4][2];
#pragma unroll
            for (int nt = 0; nt < 4; nt++) {
                int col = wn + nt * 8 + g;
                bf[nt][0] = to_tf32(Bs[s][ks * 8 + tg][col]);
                bf[nt][1] = to_tf32(Bs[s][ks * 8 + tg + 4][col]);
            }
#pragma unroll
            for (int mt = 0; mt < 2; mt++)
#pragma unroll
                for (int nt = 0; nt < 4; nt++)
                    mma_tf32(acc[mt][nt], af[mt], bf[nt]);
        }
        __syncthreads();
    }

    // epilogue
#pragma unroll
    for (int mt = 0; mt < 2; mt++) {
        int r0 = bm + wm + mt * 16 + g;
#pragma unroll
        for (int nt = 0; nt < 4; nt++) {
            int col = bn + wn + nt * 8 + 2 * tg;
            if (col < N) {   // N even, col even => col+1 < N too
                size_t o0 = (size_t)r0 * N + col;
                size_t o1 = (size_t)(r0 + 8) * N + col;
                if (acc_flag) {
                    C[o0]     += acc[mt][nt][0];
                    C[o0 + 1] += acc[mt][nt][1];
                    C[o1]     += acc[mt][nt][2];
                    C[o1 + 1] += acc[mt][nt][3];
                } else {
                    C[o0]     = acc[mt][nt][0];
                    C[o0 + 1] = acc[mt][nt][1];
                    C[o1]     = acc[mt][nt][2];
                    C[o1 + 1] = acc[mt][nt][3];
                }
            }
        }
    }
}

// ---------------- fp32 tiled SGEMM (kept for the tiny K=46 input GEMM) ------
__global__ void __launch_bounds__(128) sgemm_k(
    const float* __restrict__ A, const float* __restrict__ B,
    const float* __restrict__ bias, float* __restrict__ C,
    int M, int N, int K, int acc_flag)
{
    __shared__ __align__(16) float As[16][68];
    __shared__ __align__(16) float Bs[16][64];
    const int bm = blockIdx.y * 64;
    const int bn = blockIdx.x * 64;
    const int tid = threadIdx.x;
    const int tx = tid & 7;
    const int ty = tid >> 3;
    const int aRow = tid >> 4;
    const int aCol = tid & 15;
    const int bRow = tid >> 6;
    const int bCol = tid & 63;

    float acc[4][8];
#pragma unroll
    for (int i = 0; i < 4; i++)
#pragma unroll
        for (int j = 0; j < 8; j++) acc[i][j] = 0.f;

    for (int k0 = 0; k0 < K; k0 += 16) {
#pragma unroll
        for (int i = 0; i < 8; i++) {
            int m = bm + aRow + 8 * i;
            int k = k0 + aCol;
            As[aCol][aRow + 8 * i] = (k < K) ? A[(size_t)m * K + k] : 0.f;
        }
#pragma unroll
        for (int i = 0; i < 8; i++) {
            int k = k0 + bRow + 2 * i;
            int n = bn + bCol;
            Bs[bRow + 2 * i][bCol] = (k < K && n < N) ? B[(size_t)k * N + n] : 0.f;
        }
        __syncthreads();
#pragma unroll
        for (int k = 0; k < 16; k++) {
            float4 a4  = *(const float4*)&As[k][ty * 4];
            float4 b4a = *(const float4*)&Bs[k][tx * 8];
            float4 b4b = *(const float4*)&Bs[k][tx * 8 + 4];
            float a[4]  = {a4.x, a4.y, a4.z, a4.w};
            float bb[8] = {b4a.x, b4a.y, b4a.z, b4a.w, b4b.x, b4b.y, b4b.z, b4b.w};
#pragma unroll
            for (int i = 0; i < 4; i++)
#pragma unroll
                for (int j = 0; j < 8; j++)
                    acc[i][j] = fmaf(a[i], bb[j], acc[i][j]);
        }
        __syncthreads();
    }
#pragma unroll
    for (int i = 0; i < 4; i++) {
        int m = bm + ty * 4 + i;
#pragma unroll
        for (int j = 0; j < 8; j++) {
            int n = bn + tx * 8 + j;
            if (n < N) {
                float v = acc[i][j];
                if (bias) v += bias[n];
                size_t off = (size_t)m * N + n;
                if (acc_flag) v += C[off];
                C[off] = v;
            }
        }
    }
}

// ---------------- depthwise causal conv (k=4) + bias + silu -----------------
__global__ void conv_silu_k(const float* __restrict__ cw, const float* __restrict__ cb)
{
    int idx = blockIdx.x * 256 + threadIdx.x;
    if (idx >= BL * CONV_DIM) return;
    int c  = idx % CONV_DIM;
    int bl = idx / CONV_DIM;
    int l  = bl % NL;
    float s = cb[c];
#pragma unroll
    for (int k = 0; k < 4; k++) {
        int lk = l - 3 + k;
        if (lk >= 0)
            s = fmaf(g_zx[(size_t)(bl - 3 + k) * D_IN_PROJ + 512 + c], cw[c * 4 + k], s);
    }
    s = s / (1.f + __expf(-s));   // silu
    g_xc[idx] = s;
}

// ---------------- dt = softplus(raw + bias) ---------------------------------
__global__ void dt_k(const float* __restrict__ dtb)
{
    int idx = blockIdx.x * 256 + threadIdx.x;
    if (idx >= BL * NHEADS) return;
    int h  = idx & 7;
    int bl = idx >> 3;
    float v = g_zx[(size_t)bl * D_IN_PROJ + 1152 + h] + dtb[h];
    g_dt[idx] = (v > 20.f) ? v : log1pf(expf(v));
}

// ---------------- selective scan: one CTA per (b, head) ---------------------
__global__ void __launch_bounds__(128) scan_k(const float* __restrict__ Alog,
                                              const float* __restrict__ Dp)
{
    int bh = blockIdx.x;
    int b = bh >> 3, h = bh & 7;
    int lane = threadIdx.x & 31;
    int w = threadIdx.x >> 5;
    int p = w * 16 + (lane & 15);
    int half = (lane >> 4) & 1;

    float Ah = -__expf(Alog[h]);
    float Dh = Dp[h];

    unsigned long long st[16];
#pragma unroll
    for (int i = 0; i < 16; i++) st[i] = 0ULL;

    const float* xcb = g_xc + (size_t)b * NL * CONV_DIM;
    const float* dts = g_dt + (size_t)b * NL * NHEADS + h;
    float* yb = g_y + (size_t)b * NL * D_INNER + h * HEADDIM + p;

    for (int l = 0; l < NL; l++) {
        const float* row = xcb + (size_t)l * CONV_DIM;
        float dt = dts[(size_t)l * NHEADS];
        float dA = __expf(dt * Ah);
        float xv = row[h * HEADDIM + p];
        float dtx = dt * xv;
        const float4* B4 = (const float4*)(row + 512 + 32 * half);
        const float4* C4 = (const float4*)(row + 576 + 32 * half);
        unsigned long long dA2 = pk2(dA, dA);
        unsigned long long dx2 = pk2(dtx, dtx);
        unsigned long long ya = 0ULL;
#pragma unroll
        for (int j = 0; j < 8; j++) {
            float4 Bv = B4[j];
            float4 Cv = C4[j];
            unsigned long long b0 = pk2(Bv.x, Bv.y);
            unsigned long long b1 = pk2(Bv.z, Bv.w);
            unsigned long long c0 = pk2(Cv.x, Cv.y);
            unsigned long long c1 = pk2(Cv.z, Cv.w);
            st[2 * j]     = fma2(st[2 * j],     dA2, mul2(dx2, b0));
            ya            = fma2(st[2 * j],     c0, ya);
            st[2 * j + 1] = fma2(st[2 * j + 1], dA2, mul2(dx2, b1));
            ya            = fma2(st[2 * j + 1], c1, ya);
        }
        float y0, y1;
        upk2(ya, y0, y1);
        float ys = y0 + y1;
        ys += __shfl_xor_sync(0xffffffffu, ys, 16);
        if (!(lane & 16))
            yb[(size_t)l * D_INNER] = fmaf(Dh, xv, ys);
    }
}

// ---------------- y = rmsnorm(y * silu(z)) * rms_w, one CTA per (b,l) row ---
__global__ void __launch_bounds__(128) gate_rms_k(const float* __restrict__ rmsw)
{
    int row = blockIdx.x;
    int t = threadIdx.x;
    const float4* y4 = (const float4*)(g_y  + (size_t)row * D_INNER);
    const float4* z4 = (const float4*)(g_zx + (size_t)row * D_IN_PROJ);
    float4 yv = y4[t];
    float4 zv = z4[t];
    float4 g;
    g.x = yv.x * (zv.x / (1.f + __expf(-zv.x)));
    g.y = yv.y * (zv.y / (1.f + __expf(-zv.y)));
    g.z = yv.z * (zv.z / (1.f + __expf(-zv.z)));
    g.w = yv.w * (zv.w / (1.f + __expf(-zv.w)));
    float ss = g.x * g.x + g.y * g.y + g.z * g.z + g.w * g.w;
#pragma unroll
    for (int o = 16; o > 0; o >>= 1) ss += __shfl_xor_sync(0xffffffffu, ss, o);
    __shared__ float sb[4];
    if ((t & 31) == 0) sb[t >> 5] = ss;
    __syncthreads();
    float tot = sb[0] + sb[1] + sb[2] + sb[3];
    float sc = rsqrtf(tot * (1.f / 512.f) + 1e-5f);
    const float4* w4 = (const float4*)rmsw;
    float4 wv = w4[t];
    float4 o;
    o.x = g.x * sc * wv.x;
    o.y = g.y * sc * wv.y;
    o.z = g.z * sc * wv.z;
    o.w = g.w * sc * wv.w;
    ((float4*)(g_y + (size_t)row * D_INNER))[t] = o;
}

// ---------------- final LayerNorm (per row) + partial mean over l -----------
__global__ void __launch_bounds__(256) ln_part_k()
{
    __shared__ float sb[8];
    int b = blockIdx.x;
    int chunk = blockIdx.y;
    int c = threadIdx.x;
    int lane = c & 31, wid = c >> 5;
    float acc = 0.f;
    for (int i = 0; i < 64; i++) {
        int l = chunk * 64 + i;
        float v = g_h[((size_t)(b * NL + l)) * D_MODEL + c];
        float s = v;
#pragma unroll
        for (int o = 16; o > 0; o >>= 1) s += __shfl_xor_sync(0xffffffffu, s, o);
        if (lane == 0) sb[wid] = s;
        __syncthreads();
        float tot = sb[0] + sb[1] + sb[2] + sb[3] + sb[4] + sb[5] + sb[6] + sb[7];
        __syncthreads();
        float mu = tot * (1.f / 256.f);
        float d = v - mu;
        float s2 = d * d;
#pragma unroll
        for (int o = 16; o > 0; o >>= 1) s2 += __shfl_xor_sync(0xffffffffu, s2, o);
        if (lane == 0) sb[wid] = s2;
        __syncthreads();
        float var = (sb[0] + sb[1] + sb[2] + sb[3] + sb[4] + sb[5] + sb[6] + sb[7]) * (1.f / 256.f);
        __syncthreads();
        acc += d * rsqrtf(var + 1e-5f);
    }
    g_part[((size_t)(b * 32 + chunk)) * D_MODEL + c] = acc;
}

// ---------------- reduce partials, apply LN affine, compute heads -----------
__global__ void __launch_bounds__(256) final_k(
    const float* __restrict__ lnw, const float* __restrict__ lnb,
    const float* __restrict__ dirw, const float* __restrict__ dirb,
    const float* __restrict__ regw, const float* __restrict__ regb,
    float* __restrict__ out)
{
    __shared__ float hb[NB * D_MODEL];
    int t = threadIdx.x;
#pragma unroll
    for (int i = 0; i < (NB * D_MODEL) / 256; i++) {
        int idx = t + i * 256;
        int c = idx & 255;
        int bb = idx >> 8;
        float s = 0.f;
#pragma unroll
        for (int j = 0; j < 32; j++)
            s += g_part[((size_t)(bb * 32 + j)) * D_MODEL + c];
        hb[idx] = s * (1.f / 2048.f) * lnw[c] + lnb[c];
    }
    __syncthreads();
    if (t < NB) {
        float s = dirb[0];
        for (int c = 0; c < D_MODEL; c++) s += hb[t * D_MODEL + c] * dirw[c];
        out[t] = s;
    } else if (t < NB + NB * 3) {
        int q = t - NB;
        int bb = q / 3, j = q % 3;
        float s = regb[j];
        for (int c = 0; c < D_MODEL; c++) s += hb[bb * D_MODEL + c] * regw[c * 3 + j];
        out[NB + q] = s;
    }
}

// ---------------- launch ----------------------------------------------------
extern "C" void kernel_launch(void* const* d_in, const int* in_sizes, int n_in,
                              void* d_out, int out_size)
{
    const float* x    = (const float*)d_in[0];
    const float* inpw = (const float*)d_in[1];
    const float* inpb = (const float*)d_in[2];
    const float* ipw  = (const float*)d_in[3];
    const float* cw   = (const float*)d_in[4];
    const float* cb   = (const float*)d_in[5];
    const float* dtb  = (const float*)d_in[6];
    const float* alog = (const float*)d_in[7];
    const float* Dp   = (const float*)d_in[8];
    const float* rmsw = (const float*)d_in[9];
    const float* opw  = (const float*)d_in[10];
    const float* lnw  = (const float*)d_in[11];
    const float* lnb  = (const float*)d_in[12];
    const float* dirw = (const float*)d_in[13];
    const float* dirb = (const float*)d_in[14];
    const float* regw = (const float*)d_in[15];
    const float* regb = (const float*)d_in[16];
    float* out = (float*)d_out;

    void *ph_, *pzx_, *py_;
    cudaGetSymbolAddress(&ph_,  g_h);
    cudaGetSymbolAddress(&pzx_, g_zx);
    cudaGetSymbolAddress(&py_,  g_y);
    float* ph  = (float*)ph_;
    float* pzx = (float*)pzx_;
    float* py  = (float*)py_;

    // h = x @ inp_w + inp_b            [32768 x 256, K=46]  (fp32, tiny)
    sgemm_k<<<dim3(D_MODEL / 64, BL / 64), 128>>>(x, inpw, inpb, ph, BL, D_MODEL, NF, 0);

    for (int i = 0; i < N_LAYERS; i++) {
        // zxbcdt = h @ in_proj_w       [32768 x 1160, K=256]  (tf32 tensor)
        tf32gemm_k<<<dim3((D_IN_PROJ + 63) / 64, BL / 128), 256>>>(
            ph, ipw + (size_t)i * D_MODEL * D_IN_PROJ, pzx,
            BL, D_IN_PROJ, D_MODEL, 0);
        // conv + silu over xBC
        conv_silu_k<<<(BL * CONV_DIM + 255) / 256, 256>>>(
            cw + (size_t)i * CONV_DIM * 4, cb + (size_t)i * CONV_DIM);
        // dt = softplus(dt_raw + dt_bias)
        dt_k<<<(BL * NHEADS + 255) / 256, 256>>>(dtb + i * NHEADS);
        // selective scan (+ D*x skip)
        scan_k<<<NB * NHEADS, 128>>>(alog + i * NHEADS, Dp + i * NHEADS);
        // y = rmsnorm(y * silu(z)) * rms_w
        gate_rms_k<<<BL, 128>>>(rmsw + (size_t)i * D_INNER);
        // h += y @ out_proj_w          [32768 x 256, K=512]  (tf32 tensor, accumulate)
        tf32gemm_k<<<dim3(D_MODEL / 64, BL / 128), 256>>>(
            py, opw + (size_t)i * D_INNER * D_MODEL, ph,
            BL, D_MODEL, D_INNER, 1);
    }

    ln_part_k<<<dim3(NB, 32), 256>>>();
    final_k<<<1, 256>>>(lnw, lnb, dirw, dirb, regw, regb, out);
}

// round 3
// speedup vs baseline: 2.9566x; 2.3941x over previous
#include <cuda_runtime.h>
#include <cstdint>

#define NB 16
#define NL 2048
#define NF 46
#define D_MODEL 256
#define D_INNER 512
#define D_STATE 64
#define NHEADS 8
#define HEADDIM 64
#define CONV_DIM 640
#define D_IN_PROJ 1160
#define N_LAYERS 4
#define BL (NB*NL)

// ---------------- scratch (static device globals; no runtime allocation) ----
__device__ float g_h[(size_t)BL * D_MODEL];      // residual stream
__device__ float g_zx[(size_t)BL * D_IN_PROJ];   // in_proj output
__device__ float g_xc[(size_t)BL * CONV_DIM];    // conv+silu output
__device__ float g_sd[(size_t)BL * NHEADS * 2];  // (dA, dt) pairs, [b*8+h][l]
__device__ float g_y[(size_t)BL * D_INNER];      // scan output / gated-norm
__device__ float g_part[NB * 32 * D_MODEL];      // LN partial sums

// ---------------- packed f32x2 helpers (sm_103a) ----------------------------
__device__ __forceinline__ unsigned long long pk2(float x, float y) {
    unsigned long long r;
    asm("mov.b64 %0, {%1, %2};" : "=l"(r) : "f"(x), "f"(y));
    return r;
}
__device__ __forceinline__ void upk2(unsigned long long v, float &x, float &y) {
    asm("mov.b64 {%0, %1}, %2;" : "=f"(x), "=f"(y) : "l"(v));
}
__device__ __forceinline__ unsigned long long fma2(unsigned long long a,
                                                   unsigned long long b,
                                                   unsigned long long c) {
    unsigned long long d;
    asm("fma.rn.f32x2 %0, %1, %2, %3;" : "=l"(d) : "l"(a), "l"(b), "l"(c));
    return d;
}
__device__ __forceinline__ unsigned long long mul2(unsigned long long a,
                                                   unsigned long long b) {
    unsigned long long d;
    asm("mul.rn.f32x2 %0, %1, %2;" : "=l"(d) : "l"(a), "l"(b));
    return d;
}

// ---------------- tf32 / cp.async helpers ------------------------------------
__device__ __forceinline__ uint32_t to_tf32(float x) {
    uint32_t r;
    asm("cvt.rna.tf32.f32 %0, %1;" : "=r"(r) : "f"(x));
    return r;
}
__device__ __forceinline__ void cpa16(void* dst, const void* src) {
    uint32_t d = (uint32_t)__cvta_generic_to_shared(dst);
    asm volatile("cp.async.cg.shared.global [%0], [%1], 16;" :: "r"(d), "l"(src));
}
__device__ __forceinline__ void cpa16z(void* dst, const void* src, int bytes) {
    uint32_t d = (uint32_t)__cvta_generic_to_shared(dst);
    asm volatile("cp.async.cg.shared.global [%0], [%1], 16, %2;"
                 :: "r"(d), "l"(src), "r"(bytes));
}
__device__ __forceinline__ void cpa_commit() { asm volatile("cp.async.commit_group;"); }
__device__ __forceinline__ void cpa_wait0()  { asm volatile("cp.async.wait_group 0;"); }

__device__ __forceinline__ void mma_tf32(float c[4], const uint32_t a[4], const uint32_t b[2]) {
    asm volatile(
        "mma.sync.aligned.m16n8k8.row.col.f32.tf32.tf32.f32 "
        "{%0,%1,%2,%3}, {%4,%5,%6,%7}, {%8,%9}, {%0,%1,%2,%3};"
        : "+f"(c[0]), "+f"(c[1]), "+f"(c[2]), "+f"(c[3])
        : "r"(a[0]), "r"(a[1]), "r"(a[2]), "r"(a[3]), "r"(b[0]), "r"(b[1]));
}

// ---------------- tf32 tensor-core GEMM: C[M,N] (+)= A[M,K] @ B[K,N] --------
__global__ void __launch_bounds__(256) tf32gemm_k(
    const float* __restrict__ A, const float* __restrict__ B,
    float* __restrict__ C, int M, int N, int K, int acc_flag)
{
    __shared__ __align__(16) float As[2][128][20];
    __shared__ __align__(16) float Bs[2][16][72];

    const int tid  = threadIdx.x;
    const int bm   = blockIdx.y * 128;
    const int bn   = blockIdx.x * 64;
    const int warp = tid >> 5, lane = tid & 31;
    const int wm   = (warp >> 1) * 32;
    const int wn   = (warp & 1) * 32;
    const int g    = lane >> 2;
    const int tg   = lane & 3;

    float acc[2][4][4];
#pragma unroll
    for (int mt = 0; mt < 2; mt++)
#pragma unroll
        for (int nt = 0; nt < 4; nt++)
#pragma unroll
            for (int i = 0; i < 4; i++) acc[mt][nt][i] = 0.f;

    const int KT = K >> 4;
    const int b_k  = tid >> 4;
    const int b_nq = (tid & 15) * 4;

    auto load_stage = [&](int s, int k0) {
#pragma unroll
        for (int i = 0; i < 2; i++) {
            int idx = tid * 2 + i;
            int m = idx >> 2, kq = (idx & 3) * 4;
            cpa16(&As[s][m][kq], A + (size_t)(bm + m) * K + k0 + kq);
        }
        {
            int n = bn + b_nq;
            int nc = n < N - 4 ? n : N - 4;
            int bytes = (n < N) ? ((N - n) * 4 < 16 ? (N - n) * 4 : 16) : 0;
            cpa16z(&Bs[s][b_k][b_nq], B + (size_t)(k0 + b_k) * N + nc, bytes);
        }
        cpa_commit();
    };

    load_stage(0, 0);

    for (int kt = 0; kt < KT; kt++) {
        cpa_wait0();
        __syncthreads();
        if (kt + 1 < KT) load_stage((kt + 1) & 1, (kt + 1) * 16);
        const int s = kt & 1;
#pragma unroll
        for (int ks = 0; ks < 2; ks++) {
            uint32_t af[2][4];
#pragma unroll
            for (int mt = 0; mt < 2; mt++) {
                int r = wm + mt * 16 + g;
                int c = ks * 8 + tg;
                af[mt][0] = to_tf32(As[s][r][c]);
                af[mt][1] = to_tf32(As[s][r + 8][c]);
                af[mt][2] = to_tf32(As[s][r][c + 4]);
                af[mt][3] = to_tf32(As[s][r + 8][c + 4]);
            }
            uint32_t bf[4][2];
#pragma unroll
            for (int nt = 0; nt < 4; nt++) {
                int col = wn + nt * 8 + g;
                bf[nt][0] = to_tf32(Bs[s][ks * 8 + tg][col]);
                bf[nt][1] = to_tf32(Bs[s][ks * 8 + tg + 4][col]);
            }
#pragma unroll
            for (int mt = 0; mt < 2; mt++)
#pragma unroll
                for (int nt = 0; nt < 4; nt++)
                    mma_tf32(acc[mt][nt], af[mt], bf[nt]);
        }
        __syncthreads();
    }

#pragma unroll
    for (int mt = 0; mt < 2; mt++) {
        int r0 = bm + wm + mt * 16 + g;
#pragma unroll
        for (int nt = 0; nt < 4; nt++) {
            int col = bn + wn + nt * 8 + 2 * tg;
            if (col < N) {
                size_t o0 = (size_t)r0 * N + col;
                size_t o1 = (size_t)(r0 + 8) * N + col;
                if (acc_flag) {
                    C[o0]     += acc[mt][nt][0];
                    C[o0 + 1] += acc[mt][nt][1];
                    C[o1]     += acc[mt][nt][2];
                    C[o1 + 1] += acc[mt][nt][3];
                } else {
                    C[o0]     = acc[mt][nt][0];
                    C[o0 + 1] = acc[mt][nt][1];
                    C[o1]     = acc[mt][nt][2];
                    C[o1 + 1] = acc[mt][nt][3];
                }
            }
        }
    }
}

// ---------------- fp32 tiled SGEMM (tiny K=46 input GEMM) -------------------
__global__ void __launch_bounds__(128) sgemm_k(
    const float* __restrict__ A, const float* __restrict__ B,
    const float* __restrict__ bias, float* __restrict__ C,
    int M, int N, int K, int acc_flag)
{
    __shared__ __align__(16) float As[16][68];
    __shared__ __align__(16) float Bs[16][64];
    const int bm = blockIdx.y * 64;
    const int bn = blockIdx.x * 64;
    const int tid = threadIdx.x;
    const int tx = tid & 7;
    const int ty = tid >> 3;
    const int aRow = tid >> 4;
    const int aCol = tid & 15;
    const int bRow = tid >> 6;
    const int bCol = tid & 63;

    float acc[4][8];
#pragma unroll
    for (int i = 0; i < 4; i++)
#pragma unroll
        for (int j = 0; j < 8; j++) acc[i][j] = 0.f;

    for (int k0 = 0; k0 < K; k0 += 16) {
#pragma unroll
        for (int i = 0; i < 8; i++) {
            int m = bm + aRow + 8 * i;
            int k = k0 + aCol;
            As[aCol][aRow + 8 * i] = (k < K) ? A[(size_t)m * K + k] : 0.f;
        }
#pragma unroll
        for (int i = 0; i < 8; i++) {
            int k = k0 + bRow + 2 * i;
            int n = bn + bCol;
            Bs[bRow + 2 * i][bCol] = (k < K && n < N) ? B[(size_t)k * N + n] : 0.f;
        }
        __syncthreads();
#pragma unroll
        for (int k = 0; k < 16; k++) {
            float4 a4  = *(const float4*)&As[k][ty * 4];
            float4 b4a = *(const float4*)&Bs[k][tx * 8];
            float4 b4b = *(const float4*)&Bs[k][tx * 8 + 4];
            float a[4]  = {a4.x, a4.y, a4.z, a4.w};
            float bb[8] = {b4a.x, b4a.y, b4a.z, b4a.w, b4b.x, b4b.y, b4b.z, b4b.w};
#pragma unroll
            for (int i = 0; i < 4; i++)
#pragma unroll
                for (int j = 0; j < 8; j++)
                    acc[i][j] = fmaf(a[i], bb[j], acc[i][j]);
        }
        __syncthreads();
    }
#pragma unroll
    for (int i = 0; i < 4; i++) {
        int m = bm + ty * 4 + i;
#pragma unroll
        for (int j = 0; j < 8; j++) {
            int n = bn + tx * 8 + j;
            if (n < N) {
                float v = acc[i][j];
                if (bias) v += bias[n];
                size_t off = (size_t)m * N + n;
                if (acc_flag) v += C[off];
                C[off] = v;
            }
        }
    }
}

// ---------------- depthwise causal conv (k=4) + bias + silu -----------------
__global__ void conv_silu_k(const float* __restrict__ cw, const float* __restrict__ cb)
{
    int idx = blockIdx.x * 256 + threadIdx.x;
    if (idx >= BL * CONV_DIM) return;
    int c  = idx % CONV_DIM;
    int bl = idx / CONV_DIM;
    int l  = bl % NL;
    float s = cb[c];
#pragma unroll
    for (int k = 0; k < 4; k++) {
        int lk = l - 3 + k;
        if (lk >= 0)
            s = fmaf(g_zx[(size_t)(bl - 3 + k) * D_IN_PROJ + 512 + c], cw[c * 4 + k], s);
    }
    s = s / (1.f + __expf(-s));   // silu
    g_xc[idx] = s;
}

// ---------------- (dA, dt) precompute: g_sd[(b*8+h)*NL + l] = (exp(dt*A), dt)
__global__ void dtprep_k(const float* __restrict__ dtb, const float* __restrict__ Alog)
{
    int idx = blockIdx.x * 256 + threadIdx.x;
    if (idx >= BL * NHEADS) return;
    int l  = idx & (NL - 1);
    int bh = idx >> 11;
    int b  = bh >> 3;
    int h  = bh & 7;
    float v = g_zx[((size_t)(b * NL + l)) * D_IN_PROJ + 1152 + h] + dtb[h];
    float dt = (v > 20.f) ? v : log1pf(expf(v));
    float dA = __expf(dt * (-__expf(Alog[h])));
    ((float2*)g_sd)[idx] = make_float2(dA, dt);
}

// ---------------- selective scan v3: pipelined smem staging ------------------
// One CTA per (b, head), 128 threads. Per-step stage = x(64f) + B(64f) + C(64f)
// + (dA,dt). Threads 0..47 own one float4 slot each with a 4-deep register
// ring (LDG 5 steps ahead); thread 48 owns the (dA,dt) float2. Double-buffered
// smem stage, one bar.sync per step. Compute reads B/C as packed u64 pairs.
__global__ void __launch_bounds__(128) scan_k(const float* __restrict__ Dp)
{
    __shared__ __align__(16) float sm[2][208];

    const int bh = blockIdx.x;
    const int b = bh >> 3, h = bh & 7;
    const int t = threadIdx.x;
    const int lane = t & 31;
    const int w = t >> 5;
    const int p = w * 16 + (lane & 15);
    const int half = (lane >> 4) & 1;
    const float Dh = Dp[h];

    const float* xcb = g_xc + (size_t)b * NL * CONV_DIM;
    const float* sdp = g_sd + (size_t)bh * NL * 2;
    float* yb = g_y + (size_t)b * NL * D_INNER + h * HEADDIM + p;

    int off_g = 0, off_s = 0;
    if (t < 16)      { off_g = h * 64 + 4 * t;     off_s = 4 * t; }
    else if (t < 32) { off_g = 512 + 4 * (t - 16); off_s = 64 + 4 * (t - 16); }
    else if (t < 48) { off_g = 576 + 4 * (t - 32); off_s = 128 + 4 * (t - 32); }

    float4 r0, r1, r2, r3;              // register ring (loader threads)
    float2 d0, d1, d2, d3;              // ring for (dA,dt) (thread 48)

    // prologue: LDG steps 0..3, STS step 0, LDG step 4 into slot 0
    if (t < 48) {
        r0 = *(const float4*)(xcb + 0 * CONV_DIM + off_g);
        r1 = *(const float4*)(xcb + 1 * CONV_DIM + off_g);
        r2 = *(const float4*)(xcb + 2 * CONV_DIM + off_g);
        r3 = *(const float4*)(xcb + 3 * CONV_DIM + off_g);
        *(float4*)(&sm[0][off_s]) = r0;
        r0 = *(const float4*)(xcb + 4 * CONV_DIM + off_g);
    } else if (t == 48) {
        d0 = *(const float2*)(sdp + 0);
        d1 = *(const float2*)(sdp + 2);
        d2 = *(const float2*)(sdp + 4);
        d3 = *(const float2*)(sdp + 6);
        *(float2*)(&sm[0][192]) = d0;
        d0 = *(const float2*)(sdp + 8);
    }
    __syncthreads();

    unsigned long long st[16];
#pragma unroll
    for (int i = 0; i < 16; i++) st[i] = 0ULL;

#define SCAN_ITER(L, RN, DN, CURP)                                             \
    {                                                                          \
        const int l_ = (L);                                                    \
        float* cur_ = sm[(CURP)];                                              \
        float* nxt_ = sm[(CURP) ^ 1];                                          \
        if (t < 48) {                                                          \
            if (l_ + 1 < NL) *(float4*)(&nxt_[off_s]) = RN;                    \
            if (l_ + 5 < NL)                                                   \
                RN = *(const float4*)(xcb + (size_t)(l_ + 5) * CONV_DIM + off_g); \
        } else if (t == 48) {                                                  \
            if (l_ + 1 < NL) *(float2*)(&nxt_[192]) = DN;                      \
            if (l_ + 5 < NL) DN = *(const float2*)(sdp + 2 * (l_ + 5));        \
        }                                                                      \
        float xv = cur_[p];                                                    \
        float2 sd_ = *(const float2*)(&cur_[192]);                             \
        float dtx = sd_.y * xv;                                                \
        unsigned long long dA2 = pk2(sd_.x, sd_.x);                            \
        unsigned long long dx2 = pk2(dtx, dtx);                                \
        const ulonglong2* Bp = (const ulonglong2*)(&cur_[64 + 32 * half]);     \
        const ulonglong2* Cp = (const ulonglong2*)(&cur_[128 + 32 * half]);    \
        unsigned long long ya = 0ULL;                                          \
        _Pragma("unroll")                                                      \
        for (int j = 0; j < 8; j++) {                                          \
            ulonglong2 bv = Bp[j];                                             \
            ulonglong2 cv = Cp[j];                                             \
            st[2 * j]     = fma2(st[2 * j],     dA2, mul2(dx2, bv.x));         \
            ya            = fma2(st[2 * j],     cv.x, ya);                     \
            st[2 * j + 1] = fma2(st[2 * j + 1], dA2, mul2(dx2, bv.y));         \
            ya            = fma2(st[2 * j + 1], cv.y, ya);                     \
        }                                                                      \
        float y0_, y1_;                                                        \
        upk2(ya, y0_, y1_);                                                    \
        float ys = y0_ + y1_;                                                  \
        ys += __shfl_xor_sync(0xffffffffu, ys, 16);                            \
        if (!(lane & 16))                                                      \
            yb[(size_t)l_ * D_INNER] = fmaf(Dh, xv, ys);                       \
        __syncthreads();                                                       \
    }

    for (int l0 = 0; l0 < NL; l0 += 4) {
        SCAN_ITER(l0 + 0, r1, d1, 0)
        SCAN_ITER(l0 + 1, r2, d2, 1)
        SCAN_ITER(l0 + 2, r3, d3, 0)
        SCAN_ITER(l0 + 3, r0, d0, 1)
    }
#undef SCAN_ITER
}

// ---------------- y = rmsnorm(y * silu(z)) * rms_w, one CTA per (b,l) row ---
__global__ void __launch_bounds__(128) gate_rms_k(const float* __restrict__ rmsw)
{
    int row = blockIdx.x;
    int t = threadIdx.x;
    const float4* y4 = (const float4*)(g_y  + (size_t)row * D_INNER);
    const float4* z4 = (const float4*)(g_zx + (size_t)row * D_IN_PROJ);
    float4 yv = y4[t];
    float4 zv = z4[t];
    float4 g;
    g.x = yv.x * (zv.x / (1.f + __expf(-zv.x)));
    g.y = yv.y * (zv.y / (1.f + __expf(-zv.y)));
    g.z = yv.z * (zv.z / (1.f + __expf(-zv.z)));
    g.w = yv.w * (zv.w / (1.f + __expf(-zv.w)));
    float ss = g.x * g.x + g.y * g.y + g.z * g.z + g.w * g.w;
#pragma unroll
    for (int o = 16; o > 0; o >>= 1) ss += __shfl_xor_sync(0xffffffffu, ss, o);
    __shared__ float sb[4];
    if ((t & 31) == 0) sb[t >> 5] = ss;
    __syncthreads();
    float tot = sb[0] + sb[1] + sb[2] + sb[3];
    float sc = rsqrtf(tot * (1.f / 512.f) + 1e-5f);
    const float4* w4 = (const float4*)rmsw;
    float4 wv = w4[t];
    float4 o;
    o.x = g.x * sc * wv.x;
    o.y = g.y * sc * wv.y;
    o.z = g.z * sc * wv.z;
    o.w = g.w * sc * wv.w;
    ((float4*)(g_y + (size_t)row * D_INNER))[t] = o;
}

// ---------------- final LayerNorm (per row) + partial mean over l -----------
__global__ void __launch_bounds__(256) ln_part_k()
{
    __shared__ float sb[8];
    int b = blockIdx.x;
    int chunk = blockIdx.y;
    int c = threadIdx.x;
    int lane = c & 31, wid = c >> 5;
    float acc = 0.f;
    for (int i = 0; i < 64; i++) {
        int l = chunk * 64 + i;
        float v = g_h[((size_t)(b * NL + l)) * D_MODEL + c];
        float s = v;
#pragma unroll
        for (int o = 16; o > 0; o >>= 1) s += __shfl_xor_sync(0xffffffffu, s, o);
        if (lane == 0) sb[wid] = s;
        __syncthreads();
        float tot = sb[0] + sb[1] + sb[2] + sb[3] + sb[4] + sb[5] + sb[6] + sb[7];
        __syncthreads();
        float mu = tot * (1.f / 256.f);
        float d = v - mu;
        float s2 = d * d;
#pragma unroll
        for (int o = 16; o > 0; o >>= 1) s2 += __shfl_xor_sync(0xffffffffu, s2, o);
        if (lane == 0) sb[wid] = s2;
        __syncthreads();
        float var = (sb[0] + sb[1] + sb[2] + sb[3] + sb[4] + sb[5] + sb[6] + sb[7]) * (1.f / 256.f);
        __syncthreads();
        acc += d * rsqrtf(var + 1e-5f);
    }
    g_part[((size_t)(b * 32 + chunk)) * D_MODEL + c] = acc;
}

// ---------------- reduce partials, apply LN affine, compute heads -----------
__global__ void __launch_bounds__(256) final_k(
    const float* __restrict__ lnw, const float* __restrict__ lnb,
    const float* __restrict__ dirw, const float* __restrict__ dirb,
    const float* __restrict__ regw, const float* __restrict__ regb,
    float* __restrict__ out)
{
    __shared__ float hb[NB * D_MODEL];
    int t = threadIdx.x;
#pragma unroll
    for (int i = 0; i < (NB * D_MODEL) / 256; i++) {
        int idx = t + i * 256;
        int c = idx & 255;
        int bb = idx >> 8;
        float s = 0.f;
#pragma unroll
        for (int j = 0; j < 32; j++)
            s += g_part[((size_t)(bb * 32 + j)) * D_MODEL + c];
        hb[idx] = s * (1.f / 2048.f) * lnw[c] + lnb[c];
    }
    __syncthreads();
    if (t < NB) {
        float s = dirb[0];
        for (int c = 0; c < D_MODEL; c++) s += hb[t * D_MODEL + c] * dirw[c];
        out[t] = s;
    } else if (t < NB + NB * 3) {
        int q = t - NB;
        int bb = q / 3, j = q % 3;
        float s = regb[j];
        for (int c = 0; c < D_MODEL; c++) s += hb[bb * D_MODEL + c] * regw[c * 3 + j];
        out[NB + q] = s;
    }
}

// ---------------- launch ----------------------------------------------------
extern "C" void kernel_launch(void* const* d_in, const int* in_sizes, int n_in,
                              void* d_out, int out_size)
{
    const float* x    = (const float*)d_in[0];
    const float* inpw = (const float*)d_in[1];
    const float* inpb = (const float*)d_in[2];
    const float* ipw  = (const float*)d_in[3];
    const float* cw   = (const float*)d_in[4];
    const float* cb   = (const float*)d_in[5];
    const float* dtb  = (const float*)d_in[6];
    const float* alog = (const float*)d_in[7];
    const float* Dp   = (const float*)d_in[8];
    const float* rmsw = (const float*)d_in[9];
    const float* opw  = (const float*)d_in[10];
    const float* lnw  = (const float*)d_in[11];
    const float* lnb  = (const float*)d_in[12];
    const float* dirw = (const float*)d_in[13];
    const float* dirb = (const float*)d_in[14];
    const float* regw = (const float*)d_in[15];
    const float* regb = (const float*)d_in[16];
    float* out = (float*)d_out;

    void *ph_, *pzx_, *py_;
    cudaGetSymbolAddress(&ph_,  g_h);
    cudaGetSymbolAddress(&pzx_, g_zx);
    cudaGetSymbolAddress(&py_,  g_y);
    float* ph  = (float*)ph_;
    float* pzx = (float*)pzx_;
    float* py  = (float*)py_;

    // h = x @ inp_w + inp_b            [32768 x 256, K=46]  (fp32, tiny)
    sgemm_k<<<dim3(D_MODEL / 64, BL / 64), 128>>>(x, inpw, inpb, ph, BL, D_MODEL, NF, 0);

    for (int i = 0; i < N_LAYERS; i++) {
        // zxbcdt = h @ in_proj_w       [32768 x 1160, K=256]  (tf32 tensor)
        tf32gemm_k<<<dim3((D_IN_PROJ + 63) / 64, BL / 128), 256>>>(
            ph, ipw + (size_t)i * D_MODEL * D_IN_PROJ, pzx,
            BL, D_IN_PROJ, D_MODEL, 0);
        // conv + silu over xBC
        conv_silu_k<<<(BL * CONV_DIM + 255) / 256, 256>>>(
            cw + (size_t)i * CONV_DIM * 4, cb + (size_t)i * CONV_DIM);
        // (dA, dt) precompute
        dtprep_k<<<(BL * NHEADS + 255) / 256, 256>>>(dtb + i * NHEADS, alog + i * NHEADS);
        // selective scan (+ D*x skip), pipelined
        scan_k<<<NB * NHEADS, 128>>>(Dp + i * NHEADS);
        // y = rmsnorm(y * silu(z)) * rms_w
        gate_rms_k<<<BL, 128>>>(rmsw + (size_t)i * D_INNER);
        // h += y @ out_proj_w          [32768 x 256, K=512]  (tf32 tensor, accumulate)
        tf32gemm_k<<<dim3(D_MODEL / 64, BL / 128), 256>>>(
            py, opw + (size_t)i * D_INNER * D_MODEL, ph,
            BL, D_MODEL, D_INNER, 1);
    }

    ln_part_k<<<dim3(NB, 32), 256>>>();
    final_k<<<1, 256>>>(lnw, lnb, dirw, dirb, regw, regb, out);
}

// round 4
// speedup vs baseline: 3.3804x; 1.1433x over previous
#include <cuda_runtime.h>
#include <cstdint>

#define NB 16
#define NL 2048
#define NF 46
#define D_MODEL 256
#define D_INNER 512
#define D_STATE 64
#define NHEADS 8
#define HEADDIM 64
#define CONV_DIM 640
#define D_IN_PROJ 1160
#define N_LAYERS 4
#define BL (NB*NL)

// ---------------- scratch (static device globals; no runtime allocation) ----
__device__ float g_h[(size_t)BL * D_MODEL];      // residual stream
__device__ float g_zx[(size_t)BL * D_IN_PROJ];   // in_proj output
__device__ float g_xc[(size_t)BL * CONV_DIM];    // conv+silu output
__device__ float g_sd[(size_t)BL * NHEADS * 2];  // (dA, dt) pairs, [b*8+h][l]
__device__ float g_y[(size_t)BL * D_INNER];      // scan output / gated-norm
__device__ float g_part[NB * 32 * D_MODEL];      // LN partial sums

// ---------------- packed f32x2 helpers (sm_103a) ----------------------------
__device__ __forceinline__ unsigned long long pk2(float x, float y) {
    unsigned long long r;
    asm("mov.b64 %0, {%1, %2};" : "=l"(r) : "f"(x), "f"(y));
    return r;
}
__device__ __forceinline__ void upk2(unsigned long long v, float &x, float &y) {
    asm("mov.b64 {%0, %1}, %2;" : "=f"(x), "=f"(y) : "l"(v));
}
__device__ __forceinline__ unsigned long long fma2(unsigned long long a,
                                                   unsigned long long b,
                                                   unsigned long long c) {
    unsigned long long d;
    asm("fma.rn.f32x2 %0, %1, %2, %3;" : "=l"(d) : "l"(a), "l"(b), "l"(c));
    return d;
}
__device__ __forceinline__ unsigned long long mul2(unsigned long long a,
                                                   unsigned long long b) {
    unsigned long long d;
    asm("mul.rn.f32x2 %0, %1, %2;" : "=l"(d) : "l"(a), "l"(b));
    return d;
}

// ---------------- tf32 / cp.async helpers ------------------------------------
__device__ __forceinline__ uint32_t to_tf32(float x) {
    uint32_t r;
    asm("cvt.rna.tf32.f32 %0, %1;" : "=r"(r) : "f"(x));
    return r;
}
__device__ __forceinline__ void cpa16(void* dst, const void* src) {
    uint32_t d = (uint32_t)__cvta_generic_to_shared(dst);
    asm volatile("cp.async.cg.shared.global [%0], [%1], 16;" :: "r"(d), "l"(src));
}
__device__ __forceinline__ void cpa16z(void* dst, const void* src, int bytes) {
    uint32_t d = (uint32_t)__cvta_generic_to_shared(dst);
    asm volatile("cp.async.cg.shared.global [%0], [%1], 16, %2;"
                 :: "r"(d), "l"(src), "r"(bytes));
}
__device__ __forceinline__ void cpa_commit() { asm volatile("cp.async.commit_group;"); }
__device__ __forceinline__ void cpa_wait1()  { asm volatile("cp.async.wait_group 1;"); }

__device__ __forceinline__ void mma_tf32(float c[4], const uint32_t a[4], const uint32_t b[2]) {
    asm volatile(
        "mma.sync.aligned.m16n8k8.row.col.f32.tf32.tf32.f32 "
        "{%0,%1,%2,%3}, {%4,%5,%6,%7}, {%8,%9}, {%0,%1,%2,%3};"
        : "+f"(c[0]), "+f"(c[1]), "+f"(c[2]), "+f"(c[3])
        : "r"(a[0]), "r"(a[1]), "r"(a[2]), "r"(a[3]), "r"(b[0]), "r"(b[1]));
}

// ---------------- tf32 tensor-core GEMM: C[M,N] (+)= A[M,K] @ B[K,N] --------
// BM=128, BN=64, BK=16, 256 threads, 3-stage cp.async pipeline.
__global__ void __launch_bounds__(256) tf32gemm_k(
    const float* __restrict__ A, const float* __restrict__ B,
    float* __restrict__ C, int M, int N, int K, int acc_flag)
{
    __shared__ __align__(16) float As[3][128][20];
    __shared__ __align__(16) float Bs[3][16][72];

    const int tid  = threadIdx.x;
    const int bm   = blockIdx.y * 128;
    const int bn   = blockIdx.x * 64;
    const int warp = tid >> 5, lane = tid & 31;
    const int wm   = (warp >> 1) * 32;
    const int wn   = (warp & 1) * 32;
    const int g    = lane >> 2;
    const int tg   = lane & 3;

    float acc[2][4][4];
#pragma unroll
    for (int mt = 0; mt < 2; mt++)
#pragma unroll
        for (int nt = 0; nt < 4; nt++)
#pragma unroll
            for (int i = 0; i < 4; i++) acc[mt][nt][i] = 0.f;

    const int KT = K >> 4;
    const int b_k  = tid >> 4;
    const int b_nq = (tid & 15) * 4;

    auto load_stage = [&](int s, int k0) {
#pragma unroll
        for (int i = 0; i < 2; i++) {
            int idx = tid * 2 + i;
            int m = idx >> 2, kq = (idx & 3) * 4;
            cpa16(&As[s][m][kq], A + (size_t)(bm + m) * K + k0 + kq);
        }
        {
            int n = bn + b_nq;
            int nc = n < N - 4 ? n : N - 4;
            int bytes = (n < N) ? ((N - n) * 4 < 16 ? (N - n) * 4 : 16) : 0;
            cpa16z(&Bs[s][b_k][b_nq], B + (size_t)(k0 + b_k) * N + nc, bytes);
        }
        cpa_commit();
    };

    load_stage(0, 0);
    if (KT > 1) load_stage(1, 16);

    for (int kt = 0; kt < KT; kt++) {
        cpa_wait1();
        __syncthreads();
        if (kt + 2 < KT) load_stage((kt + 2) % 3, (kt + 2) * 16);
        const int s = kt % 3;
#pragma unroll
        for (int ks = 0; ks < 2; ks++) {
            uint32_t af[2][4];
#pragma unroll
            for (int mt = 0; mt < 2; mt++) {
                int r = wm + mt * 16 + g;
                int c = ks * 8 + tg;
                af[mt][0] = to_tf32(As[s][r][c]);
                af[mt][1] = to_tf32(As[s][r + 8][c]);
                af[mt][2] = to_tf32(As[s][r][c + 4]);
                af[mt][3] = to_tf32(As[s][r + 8][c + 4]);
            }
            uint32_t bf[4][2];
#pragma unroll
            for (int nt = 0; nt < 4; nt++) {
                int col = wn + nt * 8 + g;
                bf[nt][0] = to_tf32(Bs[s][ks * 8 + tg][col]);
                bf[nt][1] = to_tf32(Bs[s][ks * 8 + tg + 4][col]);
            }
#pragma unroll
            for (int mt = 0; mt < 2; mt++)
#pragma unroll
                for (int nt = 0; nt < 4; nt++)
                    mma_tf32(acc[mt][nt], af[mt], bf[nt]);
        }
    }

#pragma unroll
    for (int mt = 0; mt < 2; mt++) {
        int r0 = bm + wm + mt * 16 + g;
#pragma unroll
        for (int nt = 0; nt < 4; nt++) {
            int col = bn + wn + nt * 8 + 2 * tg;
            if (col < N) {
                size_t o0 = (size_t)r0 * N + col;
                size_t o1 = (size_t)(r0 + 8) * N + col;
                if (acc_flag) {
                    C[o0]     += acc[mt][nt][0];
                    C[o0 + 1] += acc[mt][nt][1];
                    C[o1]     += acc[mt][nt][2];
                    C[o1 + 1] += acc[mt][nt][3];
                } else {
                    C[o0]     = acc[mt][nt][0];
                    C[o0 + 1] = acc[mt][nt][1];
                    C[o1]     = acc[mt][nt][2];
                    C[o1 + 1] = acc[mt][nt][3];
                }
            }
        }
    }
}

// ---------------- fp32 tiled SGEMM (tiny K=46 input GEMM) -------------------
__global__ void __launch_bounds__(128) sgemm_k(
    const float* __restrict__ A, const float* __restrict__ B,
    const float* __restrict__ bias, float* __restrict__ C,
    int M, int N, int K, int acc_flag)
{
    __shared__ __align__(16) float As[16][68];
    __shared__ __align__(16) float Bs[16][64];
    const int bm = blockIdx.y * 64;
    const int bn = blockIdx.x * 64;
    const int tid = threadIdx.x;
    const int tx = tid & 7;
    const int ty = tid >> 3;
    const int aRow = tid >> 4;
    const int aCol = tid & 15;
    const int bRow = tid >> 6;
    const int bCol = tid & 63;

    float acc[4][8];
#pragma unroll
    for (int i = 0; i < 4; i++)
#pragma unroll
        for (int j = 0; j < 8; j++) acc[i][j] = 0.f;

    for (int k0 = 0; k0 < K; k0 += 16) {
#pragma unroll
        for (int i = 0; i < 8; i++) {
            int m = bm + aRow + 8 * i;
            int k = k0 + aCol;
            As[aCol][aRow + 8 * i] = (k < K) ? A[(size_t)m * K + k] : 0.f;
        }
#pragma unroll
        for (int i = 0; i < 8; i++) {
            int k = k0 + bRow + 2 * i;
            int n = bn + bCol;
            Bs[bRow + 2 * i][bCol] = (k < K && n < N) ? B[(size_t)k * N + n] : 0.f;
        }
        __syncthreads();
#pragma unroll
        for (int k = 0; k < 16; k++) {
            float4 a4  = *(const float4*)&As[k][ty * 4];
            float4 b4a = *(const float4*)&Bs[k][tx * 8];
            float4 b4b = *(const float4*)&Bs[k][tx * 8 + 4];
            float a[4]  = {a4.x, a4.y, a4.z, a4.w};
            float bb[8] = {b4a.x, b4a.y, b4a.z, b4a.w, b4b.x, b4b.y, b4b.z, b4b.w};
#pragma unroll
            for (int i = 0; i < 4; i++)
#pragma unroll
                for (int j = 0; j < 8; j++)
                    acc[i][j] = fmaf(a[i], bb[j], acc[i][j]);
        }
        __syncthreads();
    }
#pragma unroll
    for (int i = 0; i < 4; i++) {
        int m = bm + ty * 4 + i;
#pragma unroll
        for (int j = 0; j < 8; j++) {
            int n = bn + tx * 8 + j;
            if (n < N) {
                float v = acc[i][j];
                if (bias) v += bias[n];
                size_t off = (size_t)m * N + n;
                if (acc_flag) v += C[off];
                C[off] = v;
            }
        }
    }
}

// -------- fused: depthwise conv(k=4)+bias+silu (4 ch/thread) AND dt prep ----
__global__ void __launch_bounds__(256) convdt_k(
    const float* __restrict__ cw, const float* __restrict__ cb,
    const float* __restrict__ dtb, const float* __restrict__ Alog)
{
    const int convN = BL * (CONV_DIM / 4);
    int idx = blockIdx.x * 256 + threadIdx.x;
    if (idx < convN) {
        int grp = idx % (CONV_DIM / 4);
        int bl  = idx / (CONV_DIM / 4);
        int l   = bl & (NL - 1);
        int c   = grp * 4;
        const float* base = g_zx + (size_t)bl * D_IN_PROJ + 512 + c;
        float4 w0 = *(const float4*)(cw + (size_t)(c + 0) * 4);
        float4 w1 = *(const float4*)(cw + (size_t)(c + 1) * 4);
        float4 w2 = *(const float4*)(cw + (size_t)(c + 2) * 4);
        float4 w3 = *(const float4*)(cw + (size_t)(c + 3) * 4);
        float4 bb = *(const float4*)(cb + c);
        float a0 = bb.x, a1 = bb.y, a2 = bb.z, a3 = bb.w;
        const float wk0[4] = {w0.x, w0.y, w0.z, w0.w};
        const float wk1[4] = {w1.x, w1.y, w1.z, w1.w};
        const float wk2[4] = {w2.x, w2.y, w2.z, w2.w};
        const float wk3[4] = {w3.x, w3.y, w3.z, w3.w};
#pragma unroll
        for (int k = 0; k < 4; k++) {
            if (l - 3 + k >= 0) {
                float4 v = *(const float4*)(base + (ptrdiff_t)(k - 3) * D_IN_PROJ);
                a0 = fmaf(v.x, wk0[k], a0);
                a1 = fmaf(v.y, wk1[k], a1);
                a2 = fmaf(v.z, wk2[k], a2);
                a3 = fmaf(v.w, wk3[k], a3);
            }
        }
        float4 o;
        o.x = a0 / (1.f + __expf(-a0));
        o.y = a1 / (1.f + __expf(-a1));
        o.z = a2 / (1.f + __expf(-a2));
        o.w = a3 / (1.f + __expf(-a3));
        *(float4*)(g_xc + (size_t)bl * CONV_DIM + c) = o;
    } else {
        int j = idx - convN;
        if (j < BL * NHEADS) {
            int l  = j & (NL - 1);
            int bh = j >> 11;
            int b  = bh >> 3;
            int h  = bh & 7;
            float v = g_zx[((size_t)(b * NL + l)) * D_IN_PROJ + 1152 + h] + dtb[h];
            float dt = (v > 20.f) ? v : log1pf(expf(v));
            float dA = __expf(dt * (-__expf(Alog[h])));
            ((float2*)g_sd)[j] = make_float2(dA, dt);
        }
    }
}

// ---------------- selective scan v4 ------------------------------------------
// One CTA per (b, head), 256 threads (8 warps). Thread = (p, q):
// p = w*8 + (lane&7) in [0,64), q = lane>>3 selects n in [16q, 16q+16) ->
// 8 packed f32x2 state registers. y reduced with shfl.xor(8) + shfl.xor(16).
// 4-buffer smem stage ring, one bar.sync per 2 steps. Threads 0..47 stage
// x/B/C via a 4-deep float4 register ring (LDG ~5 steps ahead); thread 48
// stages the (dA,dt) pair.
__global__ void __launch_bounds__(256) scan_k(const float* __restrict__ Dp)
{
    __shared__ __align__(16) float sm[4][208];

    const int bh = blockIdx.x;
    const int b = bh >> 3, h = bh & 7;
    const int t = threadIdx.x;
    const int lane = t & 31;
    const int w = t >> 5;
    const int p = w * 8 + (lane & 7);
    const int q = lane >> 3;
    const float Dh = Dp[h];

    const float* xcb = g_xc + (size_t)b * NL * CONV_DIM;
    const float* sdp = g_sd + (size_t)bh * NL * 2;
    float* yb = g_y + (size_t)b * NL * D_INNER + h * HEADDIM + p;

    int off_g = 0, off_s = 0;
    if (t < 16)      { off_g = h * 64 + 4 * t;     off_s = 4 * t; }
    else if (t < 32) { off_g = 512 + 4 * (t - 16); off_s = 64 + 4 * (t - 16); }
    else if (t < 48) { off_g = 576 + 4 * (t - 32); off_s = 128 + 4 * (t - 32); }

    float4 r0, r1, r2, r3;
    float2 d0, d1, d2, d3;

    // prologue: LDG 0..3; STS 0,1; LDG 4,5 into slots 0,1
    if (t < 48) {
        r0 = *(const float4*)(xcb + 0 * CONV_DIM + off_g);
        r1 = *(const float4*)(xcb + 1 * CONV_DIM + off_g);
        r2 = *(const float4*)(xcb + 2 * CONV_DIM + off_g);
        r3 = *(const float4*)(xcb + 3 * CONV_DIM + off_g);
        *(float4*)(&sm[0][off_s]) = r0;
        *(float4*)(&sm[1][off_s]) = r1;
        r0 = *(const float4*)(xcb + 4 * CONV_DIM + off_g);
        r1 = *(const float4*)(xcb + 5 * CONV_DIM + off_g);
    } else if (t == 48) {
        d0 = *(const float2*)(sdp + 0);
        d1 = *(const float2*)(sdp + 2);
        d2 = *(const float2*)(sdp + 4);
        d3 = *(const float2*)(sdp + 6);
        *(float2*)(&sm[0][192]) = d0;
        *(float2*)(&sm[1][192]) = d1;
        d0 = *(const float2*)(sdp + 8);
        d1 = *(const float2*)(sdp + 10);
    }
    __syncthreads();

    unsigned long long st[8];
#pragma unroll
    for (int i = 0; i < 8; i++) st[i] = 0ULL;

#define SCAN_STEP(L, SLOT)                                                     \
    {                                                                          \
        const float* cur_ = sm[SLOT];                                          \
        float xv = cur_[p];                                                    \
        float2 sd_ = *(const float2*)(&cur_[192]);                             \
        float dtx = sd_.y * xv;                                                \
        unsigned long long dA2 = pk2(sd_.x, sd_.x);                            \
        unsigned long long dx2 = pk2(dtx, dtx);                                \
        const ulonglong2* Bp = (const ulonglong2*)(&cur_[64 + 16 * q]);        \
        const ulonglong2* Cp = (const ulonglong2*)(&cur_[128 + 16 * q]);       \
        unsigned long long ya0 = 0ULL, ya1 = 0ULL;                             \
        _Pragma("unroll")                                                      \
        for (int j = 0; j < 4; j++) {                                          \
            ulonglong2 bv = Bp[j];                                             \
            ulonglong2 cv = Cp[j];                                             \
            st[2 * j]     = fma2(st[2 * j],     dA2, mul2(dx2, bv.x));         \
            ya0           = fma2(st[2 * j],     cv.x, ya0);                    \
            st[2 * j + 1] = fma2(st[2 * j + 1], dA2, mul2(dx2, bv.y));         \
            ya1           = fma2(st[2 * j + 1], cv.y, ya1);                    \
        }                                                                      \
        float u0, u1, v0, v1;                                                  \
        upk2(ya0, u0, u1);                                                     \
        upk2(ya1, v0, v1);                                                     \
        float ys = (u0 + u1) + (v0 + v1);                                      \
        ys += __shfl_xor_sync(0xffffffffu, ys, 8);                             \
        ys += __shfl_xor_sync(0xffffffffu, ys, 16);                            \
        if (!(lane & 24))                                                      \
            yb[(size_t)(L) * D_INNER] = fmaf(Dh, xv, ys);                      \
    }

    // PAIR: STS steps L0+2,L0+3 from (RA,RB) into slots S2,S3; LDG L0+6,L0+7
    // back into (RA,RB); compute steps L0 (slot S0), L0+1 (slot S1); bar.
#define SCAN_PAIR(L0, RA, RB, DA, DB, S0, S1, S2, S3)                          \
    {                                                                          \
        const int l0_ = (L0);                                                  \
        if (t < 48) {                                                          \
            if (l0_ + 2 < NL) *(float4*)(&sm[S2][off_s]) = RA;                 \
            if (l0_ + 3 < NL) *(float4*)(&sm[S3][off_s]) = RB;                 \
            if (l0_ + 6 < NL)                                                  \
                RA = *(const float4*)(xcb + (size_t)(l0_ + 6) * CONV_DIM + off_g); \
            if (l0_ + 7 < NL)                                                  \
                RB = *(const float4*)(xcb + (size_t)(l0_ + 7) * CONV_DIM + off_g); \
        } else if (t == 48) {                                                  \
            if (l0_ + 2 < NL) *(float2*)(&sm[S2][192]) = DA;                   \
            if (l0_ + 3 < NL) *(float2*)(&sm[S3][192]) = DB;                   \
            if (l0_ + 6 < NL) DA = *(const float2*)(sdp + 2 * (l0_ + 6));      \
            if (l0_ + 7 < NL) DB = *(const float2*)(sdp + 2 * (l0_ + 7));      \
        }                                                                      \
        SCAN_STEP(l0_,     S0)                                                 \
        SCAN_STEP(l0_ + 1, S1)                                                 \
        __syncthreads();                                                       \
    }

    for (int l0 = 0; l0 < NL; l0 += 4) {
        SCAN_PAIR(l0,     r2, r3, d2, d3, 0, 1, 2, 3)
        SCAN_PAIR(l0 + 2, r0, r1, d0, d1, 2, 3, 0, 1)
    }
#undef SCAN_PAIR
#undef SCAN_STEP
}

// ---------------- y = rmsnorm(y * silu(z)) * rms_w, one CTA per (b,l) row ---
__global__ void __launch_bounds__(128) gate_rms_k(const float* __restrict__ rmsw)
{
    int row = blockIdx.x;
    int t = threadIdx.x;
    const float4* y4 = (const float4*)(g_y  + (size_t)row * D_INNER);
    const float4* z4 = (const float4*)(g_zx + (size_t)row * D_IN_PROJ);
    float4 yv = y4[t];
    float4 zv = z4[t];
    float4 g;
    g.x = yv.x * (zv.x / (1.f + __expf(-zv.x)));
    g.y = yv.y * (zv.y / (1.f + __expf(-zv.y)));
    g.z = yv.z * (zv.z / (1.f + __expf(-zv.z)));
    g.w = yv.w * (zv.w / (1.f + __expf(-zv.w)));
    float ss = g.x * g.x + g.y * g.y + g.z * g.z + g.w * g.w;
#pragma unroll
    for (int o = 16; o > 0; o >>= 1) ss += __shfl_xor_sync(0xffffffffu, ss, o);
    __shared__ float sb[4];
    if ((t & 31) == 0) sb[t >> 5] = ss;
    __syncthreads();
    float tot = sb[0] + sb[1] + sb[2] + sb[3];
    float sc = rsqrtf(tot * (1.f / 512.f) + 1e-5f);
    const float4* w4 = (const float4*)rmsw;
    float4 wv = w4[t];
    float4 o;
    o.x = g.x * sc * wv.x;
    o.y = g.y * sc * wv.y;
    o.z = g.z * sc * wv.z;
    o.w = g.w * sc * wv.w;
    ((float4*)(g_y + (size_t)row * D_INNER))[t] = o;
}

// ---------------- final LayerNorm (per row) + partial mean over l -----------
__global__ void __launch_bounds__(256) ln_part_k()
{
    __shared__ float sb[8];
    int b = blockIdx.x;
    int chunk = blockIdx.y;
    int c = threadIdx.x;
    int lane = c & 31, wid = c >> 5;
    float acc = 0.f;
    for (int i = 0; i < 64; i++) {
        int l = chunk * 64 + i;
        float v = g_h[((size_t)(b * NL + l)) * D_MODEL + c];
        float s = v;
#pragma unroll
        for (int o = 16; o > 0; o >>= 1) s += __shfl_xor_sync(0xffffffffu, s, o);
        if (lane == 0) sb[wid] = s;
        __syncthreads();
        float tot = sb[0] + sb[1] + sb[2] + sb[3] + sb[4] + sb[5] + sb[6] + sb[7];
        __syncthreads();
        float mu = tot * (1.f / 256.f);
        float d = v - mu;
        float s2 = d * d;
#pragma unroll
        for (int o = 16; o > 0; o >>= 1) s2 += __shfl_xor_sync(0xffffffffu, s2, o);
        if (lane == 0) sb[wid] = s2;
        __syncthreads();
        float var = (sb[0] + sb[1] + sb[2] + sb[3] + sb[4] + sb[5] + sb[6] + sb[7]) * (1.f / 256.f);
        __syncthreads();
        acc += d * rsqrtf(var + 1e-5f);
    }
    g_part[((size_t)(b * 32 + chunk)) * D_MODEL + c] = acc;
}

// ---------------- reduce partials, apply LN affine, compute heads -----------
__global__ void __launch_bounds__(256) final_k(
    const float* __restrict__ lnw, const float* __restrict__ lnb,
    const float* __restrict__ dirw, const float* __restrict__ dirb,
    const float* __restrict__ regw, const float* __restrict__ regb,
    float* __restrict__ out)
{
    __shared__ float hb[NB * D_MODEL];
    int t = threadIdx.x;
#pragma unroll
    for (int i = 0; i < (NB * D_MODEL) / 256; i++) {
        int idx = t + i * 256;
        int c = idx & 255;
        int bb = idx >> 8;
        float s = 0.f;
#pragma unroll
        for (int j = 0; j < 32; j++)
            s += g_part[((size_t)(bb * 32 + j)) * D_MODEL + c];
        hb[idx] = s * (1.f / 2048.f) * lnw[c] + lnb[c];
    }
    __syncthreads();
    if (t < NB) {
        float s = dirb[0];
        for (int c = 0; c < D_MODEL; c++) s += hb[t * D_MODEL + c] * dirw[c];
        out[t] = s;
    } else if (t < NB + NB * 3) {
        int q = t - NB;
        int bb = q / 3, j = q % 3;
        float s = regb[j];
        for (int c = 0; c < D_MODEL; c++) s += hb[bb * D_MODEL + c] * regw[c * 3 + j];
        out[NB + q] = s;
    }
}

// ---------------- launch ----------------------------------------------------
extern "C" void kernel_launch(void* const* d_in, const int* in_sizes, int n_in,
                              void* d_out, int out_size)
{
    const float* x    = (const float*)d_in[0];
    const float* inpw = (const float*)d_in[1];
    const float* inpb = (const float*)d_in[2];
    const float* ipw  = (const float*)d_in[3];
    const float* cw   = (const float*)d_in[4];
    const float* cb   = (const float*)d_in[5];
    const float* dtb  = (const float*)d_in[6];
    const float* alog = (const float*)d_in[7];
    const float* Dp   = (const float*)d_in[8];
    const float* rmsw = (const float*)d_in[9];
    const float* opw  = (const float*)d_in[10];
    const float* lnw  = (const float*)d_in[11];
    const float* lnb  = (const float*)d_in[12];
    const float* dirw = (const float*)d_in[13];
    const float* dirb = (const float*)d_in[14];
    const float* regw = (const float*)d_in[15];
    const float* regb = (const float*)d_in[16];
    float* out = (float*)d_out;

    void *ph_, *pzx_, *py_;
    cudaGetSymbolAddress(&ph_,  g_h);
    cudaGetSymbolAddress(&pzx_, g_zx);
    cudaGetSymbolAddress(&py_,  g_y);
    float* ph  = (float*)ph_;
    float* pzx = (float*)pzx_;
    float* py  = (float*)py_;

    // h = x @ inp_w + inp_b            [32768 x 256, K=46]  (fp32, tiny)
    sgemm_k<<<dim3(D_MODEL / 64, BL / 64), 128>>>(x, inpw, inpb, ph, BL, D_MODEL, NF, 0);

    const int convdt_threads = BL * (CONV_DIM / 4) + BL * NHEADS;

    for (int i = 0; i < N_LAYERS; i++) {
        // zxbcdt = h @ in_proj_w       [32768 x 1160, K=256]  (tf32 tensor)
        tf32gemm_k<<<dim3((D_IN_PROJ + 63) / 64, BL / 128), 256>>>(
            ph, ipw + (size_t)i * D_MODEL * D_IN_PROJ, pzx,
            BL, D_IN_PROJ, D_MODEL, 0);
        // conv + silu over xBC, fused with (dA, dt) precompute
        convdt_k<<<(convdt_threads + 255) / 256, 256>>>(
            cw + (size_t)i * CONV_DIM * 4, cb + (size_t)i * CONV_DIM,
            dtb + i * NHEADS, alog + i * NHEADS);
        // selective scan (+ D*x skip), pipelined
        scan_k<<<NB * NHEADS, 256>>>(Dp + i * NHEADS);
        // y = rmsnorm(y * silu(z)) * rms_w
        gate_rms_k<<<BL, 128>>>(rmsw + (size_t)i * D_INNER);
        // h += y @ out_proj_w          [32768 x 256, K=512]  (tf32 tensor, accumulate)
        tf32gemm_k<<<dim3(D_MODEL / 64, BL / 128), 256>>>(
            py, opw + (size_t)i * D_INNER * D_MODEL, ph,
            BL, D_MODEL, D_INNER, 1);
    }

    ln_part_k<<<dim3(NB, 32), 256>>>();
    final_k<<<1, 256>>>(lnw, lnb, dirw, dirb, regw, regb, out);
}

// round 5
// speedup vs baseline: 4.3841x; 1.2969x over previous
#include <cuda_runtime.h>
#include <cstdint>

#define NB 16
#define NL 2048
#define NF 46
#define D_MODEL 256
#define D_INNER 512
#define D_STATE 64
#define NHEADS 8
#define HEADDIM 64
#define CONV_DIM 640
#define D_IN_PROJ 1160
#define N_LAYERS 4
#define BL (NB*NL)
#define CHUNK 32
#define NCHUNK (NL/CHUNK)

// ---------------- scratch (static device globals; no runtime allocation) ----
__device__ float g_h[(size_t)BL * D_MODEL];      // residual stream
__device__ float g_zx[(size_t)BL * D_IN_PROJ];   // in_proj output
__device__ float g_xc[(size_t)BL * CONV_DIM];    // conv+silu output
__device__ float g_sd[(size_t)BL * NHEADS * 2];  // (dtA, dt) pairs, [b*8+h][l]
__device__ float g_y[(size_t)BL * D_INNER];      // scan output / gated-norm
__device__ float g_part[NB * 32 * D_MODEL];      // LN partial sums

// ---------------- tf32 / cp.async helpers ------------------------------------
__device__ __forceinline__ uint32_t to_tf32(float x) {
    uint32_t r;
    asm("cvt.rna.tf32.f32 %0, %1;" : "=r"(r) : "f"(x));
    return r;
}
__device__ __forceinline__ void split2(float x, uint32_t &hi, uint32_t &lo) {
    uint32_t h = to_tf32(x);
    hi = h;
    lo = to_tf32(x - __uint_as_float(h));
}
__device__ __forceinline__ void cpa16(void* dst, const void* src) {
    uint32_t d = (uint32_t)__cvta_generic_to_shared(dst);
    asm volatile("cp.async.cg.shared.global [%0], [%1], 16;" :: "r"(d), "l"(src));
}
__device__ __forceinline__ void cpa16z(void* dst, const void* src, int bytes) {
    uint32_t d = (uint32_t)__cvta_generic_to_shared(dst);
    asm volatile("cp.async.cg.shared.global [%0], [%1], 16, %2;"
                 :: "r"(d), "l"(src), "r"(bytes));
}
__device__ __forceinline__ void cpa_commit() { asm volatile("cp.async.commit_group;"); }
__device__ __forceinline__ void cpa_wait0()  { asm volatile("cp.async.wait_group 0;"); }
__device__ __forceinline__ void cpa_wait1()  { asm volatile("cp.async.wait_group 1;"); }

__device__ __forceinline__ void mma_tf32(float c[4], const uint32_t a[4], const uint32_t b[2]) {
    asm volatile(
        "mma.sync.aligned.m16n8k8.row.col.f32.tf32.tf32.f32 "
        "{%0,%1,%2,%3}, {%4,%5,%6,%7}, {%8,%9}, {%0,%1,%2,%3};"
        : "+f"(c[0]), "+f"(c[1]), "+f"(c[2]), "+f"(c[3])
        : "r"(a[0]), "r"(a[1]), "r"(a[2]), "r"(a[3]), "r"(b[0]), "r"(b[1]));
}
// tf32x3: near-fp32 accuracy (hi*hi + lo*hi + hi*lo)
__device__ __forceinline__ void mma3(float c[4], const uint32_t ah[4], const uint32_t al[4],
                                     const uint32_t bh[2], const uint32_t bl[2]) {
    mma_tf32(c, ah, bh);
    mma_tf32(c, al, bh);
    mma_tf32(c, ah, bl);
}

// ---------------- tf32 tensor-core GEMM: C[M,N] (+)= A[M,K] @ B[K,N] --------
// BM=128, BN=64, BK=16, 256 threads, 3-stage cp.async pipeline.
__global__ void __launch_bounds__(256) tf32gemm_k(
    const float* __restrict__ A, const float* __restrict__ B,
    float* __restrict__ C, int M, int N, int K, int acc_flag)
{
    __shared__ __align__(16) float As[3][128][20];
    __shared__ __align__(16) float Bs[3][16][72];

    const int tid  = threadIdx.x;
    const int bm   = blockIdx.y * 128;
    const int bn   = blockIdx.x * 64;
    const int warp = tid >> 5, lane = tid & 31;
    const int wm   = (warp >> 1) * 32;
    const int wn   = (warp & 1) * 32;
    const int g    = lane >> 2;
    const int tg   = lane & 3;

    float acc[2][4][4];
#pragma unroll
    for (int mt = 0; mt < 2; mt++)
#pragma unroll
        for (int nt = 0; nt < 4; nt++)
#pragma unroll
            for (int i = 0; i < 4; i++) acc[mt][nt][i] = 0.f;

    const int KT = K >> 4;
    const int b_k  = tid >> 4;
    const int b_nq = (tid & 15) * 4;

    auto load_stage = [&](int s, int k0) {
#pragma unroll
        for (int i = 0; i < 2; i++) {
            int idx = tid * 2 + i;
            int m = idx >> 2, kq = (idx & 3) * 4;
            cpa16(&As[s][m][kq], A + (size_t)(bm + m) * K + k0 + kq);
        }
        {
            int n = bn + b_nq;
            int nc = n < N - 4 ? n : N - 4;
            int bytes = (n < N) ? ((N - n) * 4 < 16 ? (N - n) * 4 : 16) : 0;
            cpa16z(&Bs[s][b_k][b_nq], B + (size_t)(k0 + b_k) * N + nc, bytes);
        }
        cpa_commit();
    };

    load_stage(0, 0);
    if (KT > 1) load_stage(1, 16);

    for (int kt = 0; kt < KT; kt++) {
        cpa_wait1();
        __syncthreads();
        if (kt + 2 < KT) load_stage((kt + 2) % 3, (kt + 2) * 16);
        const int s = kt % 3;
#pragma unroll
        for (int ks = 0; ks < 2; ks++) {
            uint32_t af[2][4];
#pragma unroll
            for (int mt = 0; mt < 2; mt++) {
                int r = wm + mt * 16 + g;
                int c = ks * 8 + tg;
                af[mt][0] = to_tf32(As[s][r][c]);
                af[mt][1] = to_tf32(As[s][r + 8][c]);
                af[mt][2] = to_tf32(As[s][r][c + 4]);
                af[mt][3] = to_tf32(As[s][r + 8][c + 4]);
            }
            uint32_t bf[4][2];
#pragma unroll
            for (int nt = 0; nt < 4; nt++) {
                int col = wn + nt * 8 + g;
                bf[nt][0] = to_tf32(Bs[s][ks * 8 + tg][col]);
                bf[nt][1] = to_tf32(Bs[s][ks * 8 + tg + 4][col]);
            }
#pragma unroll
            for (int mt = 0; mt < 2; mt++)
#pragma unroll
                for (int nt = 0; nt < 4; nt++)
                    mma_tf32(acc[mt][nt], af[mt], bf[nt]);
        }
    }

#pragma unroll
    for (int mt = 0; mt < 2; mt++) {
        int r0 = bm + wm + mt * 16 + g;
#pragma unroll
        for (int nt = 0; nt < 4; nt++) {
            int col = bn + wn + nt * 8 + 2 * tg;
            if (col < N) {
                size_t o0 = (size_t)r0 * N + col;
                size_t o1 = (size_t)(r0 + 8) * N + col;
                if (acc_flag) {
                    C[o0]     += acc[mt][nt][0];
                    C[o0 + 1] += acc[mt][nt][1];
                    C[o1]     += acc[mt][nt][2];
                    C[o1 + 1] += acc[mt][nt][3];
                } else {
                    C[o0]     = acc[mt][nt][0];
                    C[o0 + 1] = acc[mt][nt][1];
                    C[o1]     = acc[mt][nt][2];
                    C[o1 + 1] = acc[mt][nt][3];
                }
            }
        }
    }
}

// ---------------- fp32 tiled SGEMM (tiny K=46 input GEMM) -------------------
__global__ void __launch_bounds__(128) sgemm_k(
    const float* __restrict__ A, const float* __restrict__ B,
    const float* __restrict__ bias, float* __restrict__ C,
    int M, int N, int K, int acc_flag)
{
    __shared__ __align__(16) float As[16][68];
    __shared__ __align__(16) float Bs[16][64];
    const int bm = blockIdx.y * 64;
    const int bn = blockIdx.x * 64;
    const int tid = threadIdx.x;
    const int tx = tid & 7;
    const int ty = tid >> 3;
    const int aRow = tid >> 4;
    const int aCol = tid & 15;
    const int bRow = tid >> 6;
    const int bCol = tid & 63;

    float acc[4][8];
#pragma unroll
    for (int i = 0; i < 4; i++)
#pragma unroll
        for (int j = 0; j < 8; j++) acc[i][j] = 0.f;

    for (int k0 = 0; k0 < K; k0 += 16) {
#pragma unroll
        for (int i = 0; i < 8; i++) {
            int m = bm + aRow + 8 * i;
            int k = k0 + aCol;
            As[aCol][aRow + 8 * i] = (k < K) ? A[(size_t)m * K + k] : 0.f;
        }
#pragma unroll
        for (int i = 0; i < 8; i++) {
            int k = k0 + bRow + 2 * i;
            int n = bn + bCol;
            Bs[bRow + 2 * i][bCol] = (k < K && n < N) ? B[(size_t)k * N + n] : 0.f;
        }
        __syncthreads();
#pragma unroll
        for (int k = 0; k < 16; k++) {
            float4 a4  = *(const float4*)&As[k][ty * 4];
            float4 b4a = *(const float4*)&Bs[k][tx * 8];
            float4 b4b = *(const float4*)&Bs[k][tx * 8 + 4];
            float a[4]  = {a4.x, a4.y, a4.z, a4.w};
            float bb[8] = {b4a.x, b4a.y, b4a.z, b4a.w, b4b.x, b4b.y, b4b.z, b4b.w};
#pragma unroll
            for (int i = 0; i < 4; i++)
#pragma unroll
                for (int j = 0; j < 8; j++)
                    acc[i][j] = fmaf(a[i], bb[j], acc[i][j]);
        }
        __syncthreads();
    }
#pragma unroll
    for (int i = 0; i < 4; i++) {
        int m = bm + ty * 4 + i;
#pragma unroll
        for (int j = 0; j < 8; j++) {
            int n = bn + tx * 8 + j;
            if (n < N) {
                float v = acc[i][j];
                if (bias) v += bias[n];
                size_t off = (size_t)m * N + n;
                if (acc_flag) v += C[off];
                C[off] = v;
            }
        }
    }
}

// -------- fused: depthwise conv(k=4)+bias+silu (4 ch/thread) AND dt prep ----
// dt prep now stores (dtA = dt * A, dt) — the chunked scan needs log-decay.
__global__ void __launch_bounds__(256) convdt_k(
    const float* __restrict__ cw, const float* __restrict__ cb,
    const float* __restrict__ dtb, const float* __restrict__ Alog)
{
    const int convN = BL * (CONV_DIM / 4);
    int idx = blockIdx.x * 256 + threadIdx.x;
    if (idx < convN) {
        int grp = idx % (CONV_DIM / 4);
        int bl  = idx / (CONV_DIM / 4);
        int l   = bl & (NL - 1);
        int c   = grp * 4;
        const float* base = g_zx + (size_t)bl * D_IN_PROJ + 512 + c;
        float4 w0 = *(const float4*)(cw + (size_t)(c + 0) * 4);
        float4 w1 = *(const float4*)(cw + (size_t)(c + 1) * 4);
        float4 w2 = *(const float4*)(cw + (size_t)(c + 2) * 4);
        float4 w3 = *(const float4*)(cw + (size_t)(c + 3) * 4);
        float4 bb = *(const float4*)(cb + c);
        float a0 = bb.x, a1 = bb.y, a2 = bb.z, a3 = bb.w;
        const float wk0[4] = {w0.x, w0.y, w0.z, w0.w};
        const float wk1[4] = {w1.x, w1.y, w1.z, w1.w};
        const float wk2[4] = {w2.x, w2.y, w2.z, w2.w};
        const float wk3[4] = {w3.x, w3.y, w3.z, w3.w};
#pragma unroll
        for (int k = 0; k < 4; k++) {
            if (l - 3 + k >= 0) {
                float4 v = *(const float4*)(base + (ptrdiff_t)(k - 3) * D_IN_PROJ);
                a0 = fmaf(v.x, wk0[k], a0);
                a1 = fmaf(v.y, wk1[k], a1);
                a2 = fmaf(v.z, wk2[k], a2);
                a3 = fmaf(v.w, wk3[k], a3);
            }
        }
        float4 o;
        o.x = a0 / (1.f + __expf(-a0));
        o.y = a1 / (1.f + __expf(-a1));
        o.z = a2 / (1.f + __expf(-a2));
        o.w = a3 / (1.f + __expf(-a3));
        *(float4*)(g_xc + (size_t)bl * CONV_DIM + c) = o;
    } else {
        int j = idx - convN;
        if (j < BL * NHEADS) {
            int l  = j & (NL - 1);
            int bh = j >> 11;
            int b  = bh >> 3;
            int h  = bh & 7;
            float v = g_zx[((size_t)(b * NL + l)) * D_IN_PROJ + 1152 + h] + dtb[h];
            float dt = (v > 20.f) ? v : log1pf(expf(v));
            float dtA = dt * (-__expf(Alog[h]));
            ((float2*)g_sd)[j] = make_float2(dtA, dt);
        }
    }
}

// ---------------- selective scan v5: chunked SSD via tensor cores ------------
// One CTA per (b, head), 128 threads (4 warps). Chunk T=32 => 64 sequential
// chunk steps. Per chunk (tf32x3 split for near-fp32 accuracy):
//   s_l = cumsum(dtA) inclusive (warp-0 shfl scan)
//   G   = C @ B^T                          [32x32, k=64]
//   W[l,j] = (l>=j) ? G * exp(s_l-s_j) * dt_j : 0
//   Y    = W @ X  +  diag(exp(s_l)) C @ S0^T    [32x64]
//   S1   = exp(s_31)*S0 + X^T @ diag(exp(s_31-s_j) dt_j) B   [64x64]
//   y_out = Y + D*x
__global__ void __launch_bounds__(128) scan_k(const float* __restrict__ Dp)
{
    __shared__ __align__(16) float sB[CHUNK][68];
    __shared__ __align__(16) float sC[CHUNK][68];
    __shared__ __align__(16) float sX[CHUNK][68];
    __shared__ float sW[CHUNK][36];
    __shared__ float sS[64][66];
    __shared__ __align__(16) float2 s_sd[CHUNK];
    __shared__ float s_s[CHUNK], s_dt[CHUNK], s_wq[CHUNK], s_el[CHUNK];
    __shared__ float s_ptot;

    const int bh = blockIdx.x;
    const int b = bh >> 3, h = bh & 7;
    const int t = threadIdx.x;
    const int w = t >> 5, lane = t & 31;
    const int g = lane >> 2, tg = lane & 3;
    const float Dh = Dp[h];

    const float* xcb = g_xc + (size_t)b * NL * CONV_DIM;
    const float* sdp = g_sd + (size_t)bh * NL * 2;

    // zero running state (smem mirror + register copy)
    for (int i = t; i < 64 * 66; i += 128) ((float*)sS)[i] = 0.f;
    float S[8][4];
#pragma unroll
    for (int i = 0; i < 8; i++)
#pragma unroll
        for (int r = 0; r < 4; r++) S[i][r] = 0.f;
    __syncthreads();

    const int mt = w >> 1;   // l-tile (16 rows) for GEMM1/2/3
    const int jt = w & 1;    // j 16-block for GEMM1
    const int ph = w & 1;    // p half (32 cols) for GEMM2/3

    for (int ch = 0; ch < NCHUNK; ch++) {
        const int l0 = ch * CHUNK;

        // ---- stage tiles: B, C, X slices + (dtA, dt) pairs ----
#pragma unroll
        for (int i = 0; i < 4; i++) {
            int slot = t + i * 128;
            int row = slot >> 4, c4 = (slot & 15) * 4;
            const float* src = xcb + (size_t)(l0 + row) * CONV_DIM;
            cpa16(&sB[row][c4], src + 512 + c4);
            cpa16(&sC[row][c4], src + 576 + c4);
            cpa16(&sX[row][c4], src + h * HEADDIM + c4);
        }
        if (t < 16) cpa16(((float*)s_sd) + t * 4, sdp + (size_t)l0 * 2 + t * 4);
        cpa_commit();
        cpa_wait0();
        __syncthreads();

        // ---- per-chunk decay scalars (warp 0) ----
        if (w == 0) {
            float2 sd = s_sd[lane];
            float s = sd.x;
#pragma unroll
            for (int o = 1; o < 32; o <<= 1) {
                float v = __shfl_up_sync(0xffffffffu, s, o);
                if (lane >= o) s += v;
            }
            float stot = __shfl_sync(0xffffffffu, s, 31);
            s_s[lane]  = s;
            s_dt[lane] = sd.y;
            s_wq[lane] = __expf(stot - s) * sd.y;
            s_el[lane] = __expf(s);
            if (lane == 31) s_ptot = __expf(stot);
        }
        __syncthreads();

        // ---- GEMM1: G = C @ B^T  (m=l 32, n=j 32, k=n 64) ----
        float Gacc[2][4] = {{0.f,0.f,0.f,0.f},{0.f,0.f,0.f,0.f}};
#pragma unroll
        for (int k8 = 0; k8 < 8; k8++) {
            int kc = k8 * 8 + tg;
            uint32_t ah[4], al[4];
            split2(sC[mt*16 + g][kc],       ah[0], al[0]);
            split2(sC[mt*16 + g + 8][kc],   ah[1], al[1]);
            split2(sC[mt*16 + g][kc+4],     ah[2], al[2]);
            split2(sC[mt*16 + g + 8][kc+4], ah[3], al[3]);
#pragma unroll
            for (int nt = 0; nt < 2; nt++) {
                int j = jt*16 + nt*8 + g;
                uint32_t bhv[2], blv[2];
                split2(sB[j][kc],   bhv[0], blv[0]);
                split2(sB[j][kc+4], bhv[1], blv[1]);
                mma3(Gacc[nt], ah, al, bhv, blv);
            }
        }
        // ---- build W in smem ----
        {
            int row = g, col = 2 * tg;
#pragma unroll
            for (int nt = 0; nt < 2; nt++) {
                int jb = jt*16 + nt*8 + col;
                int lb = mt*16 + row;
                const int ls[4] = {lb, lb, lb + 8, lb + 8};
                const int js[4] = {jb, jb + 1, jb, jb + 1};
#pragma unroll
                for (int r = 0; r < 4; r++) {
                    float wv = (ls[r] >= js[r])
                        ? Gacc[nt][r] * __expf(s_s[ls[r]] - s_s[js[r]]) * s_dt[js[r]]
                        : 0.f;
                    sW[ls[r]][js[r]] = wv;
                }
            }
        }
        __syncthreads();

        // ---- GEMM2 (Y += W @ X) and GEMM3 (Y += (el*C) @ S0^T) ----
        float Y[4][4] = {{0,0,0,0},{0,0,0,0},{0,0,0,0},{0,0,0,0}};
#pragma unroll
        for (int k8 = 0; k8 < 4; k8++) {                 // k = j (32)
            int kc = k8 * 8 + tg;
            uint32_t ah[4], al[4];
            split2(sW[mt*16 + g][kc],       ah[0], al[0]);
            split2(sW[mt*16 + g + 8][kc],   ah[1], al[1]);
            split2(sW[mt*16 + g][kc+4],     ah[2], al[2]);
            split2(sW[mt*16 + g + 8][kc+4], ah[3], al[3]);
#pragma unroll
            for (int nt = 0; nt < 4; nt++) {
                int p = ph*32 + nt*8 + g;
                uint32_t bhv[2], blv[2];
                split2(sX[kc][p],   bhv[0], blv[0]);
                split2(sX[kc+4][p], bhv[1], blv[1]);
                mma3(Y[nt], ah, al, bhv, blv);
            }
        }
        {
            float e0 = s_el[mt*16 + g], e1 = s_el[mt*16 + g + 8];
#pragma unroll
            for (int k8 = 0; k8 < 8; k8++) {             // k = n (64)
                int kc = k8 * 8 + tg;
                uint32_t ah[4], al[4];
                split2(e0 * sC[mt*16 + g][kc],       ah[0], al[0]);
                split2(e1 * sC[mt*16 + g + 8][kc],   ah[1], al[1]);
                split2(e0 * sC[mt*16 + g][kc+4],     ah[2], al[2]);
                split2(e1 * sC[mt*16 + g + 8][kc+4], ah[3], al[3]);
#pragma unroll
                for (int nt = 0; nt < 4; nt++) {
                    int p = ph*32 + nt*8 + g;
                    uint32_t bhv[2], blv[2];
                    split2(sS[p][kc],   bhv[0], blv[0]);
                    split2(sS[p][kc+4], bhv[1], blv[1]);
                    mma3(Y[nt], ah, al, bhv, blv);
                }
            }
        }
        // ---- y epilogue: y = Y + D*x ----
        {
            int l_a = mt*16 + g, l_b = l_a + 8;
            float* ya_ = g_y + ((size_t)(b * NL + l0 + l_a)) * D_INNER + h * HEADDIM;
            float* yb_ = g_y + ((size_t)(b * NL + l0 + l_b)) * D_INNER + h * HEADDIM;
#pragma unroll
            for (int nt = 0; nt < 4; nt++) {
                int p0 = ph*32 + nt*8 + 2*tg;
                ya_[p0]     = Y[nt][0] + Dh * sX[l_a][p0];
                ya_[p0 + 1] = Y[nt][1] + Dh * sX[l_a][p0 + 1];
                yb_[p0]     = Y[nt][2] + Dh * sX[l_b][p0];
                yb_[p0 + 1] = Y[nt][3] + Dh * sX[l_b][p0 + 1];
            }
        }

        // ---- GEMM4: S = ptot*S + X^T @ (wq ⊙ B)  (m=p 64, n=n 64, k=j 32) ----
        {
            float pt = s_ptot;
#pragma unroll
            for (int nt = 0; nt < 8; nt++)
#pragma unroll
                for (int r = 0; r < 4; r++) S[nt][r] *= pt;
#pragma unroll
            for (int k8 = 0; k8 < 4; k8++) {
                int kc = k8 * 8;
                uint32_t ah[4], al[4];
                split2(sX[kc + tg][w*16 + g],       ah[0], al[0]);
                split2(sX[kc + tg][w*16 + g + 8],   ah[1], al[1]);
                split2(sX[kc + tg + 4][w*16 + g],   ah[2], al[2]);
                split2(sX[kc + tg + 4][w*16 + g+8], ah[3], al[3]);
                float w0 = s_wq[kc + tg], w1 = s_wq[kc + tg + 4];
#pragma unroll
                for (int nt = 0; nt < 8; nt++) {
                    int n = nt*8 + g;
                    uint32_t bhv[2], blv[2];
                    split2(w0 * sB[kc + tg][n],     bhv[0], blv[0]);
                    split2(w1 * sB[kc + tg + 4][n], bhv[1], blv[1]);
                    mma3(S[nt], ah, al, bhv, blv);
                }
            }
        }
        __syncthreads();   // all warps done reading sS / tiles
        // mirror S -> sS for next chunk's GEMM3
#pragma unroll
        for (int nt = 0; nt < 8; nt++) {
            int n0 = nt*8 + 2*tg;
            sS[w*16 + g][n0]         = S[nt][0];
            sS[w*16 + g][n0 + 1]     = S[nt][1];
            sS[w*16 + g + 8][n0]     = S[nt][2];
            sS[w*16 + g + 8][n0 + 1] = S[nt][3];
        }
        __syncthreads();
    }
}

// ---------------- y = rmsnorm(y * silu(z)) * rms_w, one CTA per (b,l) row ---
__global__ void __launch_bounds__(128) gate_rms_k(const float* __restrict__ rmsw)
{
    int row = blockIdx.x;
    int t = threadIdx.x;
    const float4* y4 = (const float4*)(g_y  + (size_t)row * D_INNER);
    const float4* z4 = (const float4*)(g_zx + (size_t)row * D_IN_PROJ);
    float4 yv = y4[t];
    float4 zv = z4[t];
    float4 g;
    g.x = yv.x * (zv.x / (1.f + __expf(-zv.x)));
    g.y = yv.y * (zv.y / (1.f + __expf(-zv.y)));
    g.z = yv.z * (zv.z / (1.f + __expf(-zv.z)));
    g.w = yv.w * (zv.w / (1.f + __expf(-zv.w)));
    float ss = g.x * g.x + g.y * g.y + g.z * g.z + g.w * g.w;
#pragma unroll
    for (int o = 16; o > 0; o >>= 1) ss += __shfl_xor_sync(0xffffffffu, ss, o);
    __shared__ float sb[4];
    if ((t & 31) == 0) sb[t >> 5] = ss;
    __syncthreads();
    float tot = sb[0] + sb[1] + sb[2] + sb[3];
    float sc = rsqrtf(tot * (1.f / 512.f) + 1e-5f);
    const float4* w4 = (const float4*)rmsw;
    float4 wv = w4[t];
    float4 o;
    o.x = g.x * sc * wv.x;
    o.y = g.y * sc * wv.y;
    o.z = g.z * sc * wv.z;
    o.w = g.w * sc * wv.w;
    ((float4*)(g_y + (size_t)row * D_INNER))[t] = o;
}

// ---------------- final LayerNorm (per row) + partial mean over l -----------
__global__ void __launch_bounds__(256) ln_part_k()
{
    __shared__ float sb[8];
    int b = blockIdx.x;
    int chunk = blockIdx.y;
    int c = threadIdx.x;
    int lane = c & 31, wid = c >> 5;
    float acc = 0.f;
    for (int i = 0; i < 64; i++) {
        int l = chunk * 64 + i;
        float v = g_h[((size_t)(b * NL + l)) * D_MODEL + c];
        float s = v;
#pragma unroll
        for (int o = 16; o > 0; o >>= 1) s += __shfl_xor_sync(0xffffffffu, s, o);
        if (lane == 0) sb[wid] = s;
        __syncthreads();
        float tot = sb[0] + sb[1] + sb[2] + sb[3] + sb[4] + sb[5] + sb[6] + sb[7];
        __syncthreads();
        float mu = tot * (1.f / 256.f);
        float d = v - mu;
        float s2 = d * d;
#pragma unroll
        for (int o = 16; o > 0; o >>= 1) s2 += __shfl_xor_sync(0xffffffffu, s2, o);
        if (lane == 0) sb[wid] = s2;
        __syncthreads();
        float var = (sb[0] + sb[1] + sb[2] + sb[3] + sb[4] + sb[5] + sb[6] + sb[7]) * (1.f / 256.f);
        __syncthreads();
        acc += d * rsqrtf(var + 1e-5f);
    }
    g_part[((size_t)(b * 32 + chunk)) * D_MODEL + c] = acc;
}

// ---------------- reduce partials, apply LN affine, compute heads -----------
__global__ void __launch_bounds__(256) final_k(
    const float* __restrict__ lnw, const float* __restrict__ lnb,
    const float* __restrict__ dirw, const float* __restrict__ dirb,
    const float* __restrict__ regw, const float* __restrict__ regb,
    float* __restrict__ out)
{
    __shared__ float hb[NB * D_MODEL];
    int t = threadIdx.x;
#pragma unroll
    for (int i = 0; i < (NB * D_MODEL) / 256; i++) {
        int idx = t + i * 256;
        int c = idx & 255;
        int bb = idx >> 8;
        float s = 0.f;
#pragma unroll
        for (int j = 0; j < 32; j++)
            s += g_part[((size_t)(bb * 32 + j)) * D_MODEL + c];
        hb[idx] = s * (1.f / 2048.f) * lnw[c] + lnb[c];
    }
    __syncthreads();
    if (t < NB) {
        float s = dirb[0];
        for (int c = 0; c < D_MODEL; c++) s += hb[t * D_MODEL + c] * dirw[c];
        out[t] = s;
    } else if (t < NB + NB * 3) {
        int q = t - NB;
        int bb = q / 3, j = q % 3;
        float s = regb[j];
        for (int c = 0; c < D_MODEL; c++) s += hb[bb * D_MODEL + c] * regw[c * 3 + j];
        out[NB + q] = s;
    }
}

// ---------------- launch ----------------------------------------------------
extern "C" void kernel_launch(void* const* d_in, const int* in_sizes, int n_in,
                              void* d_out, int out_size)
{
    const float* x    = (const float*)d_in[0];
    const float* inpw = (const float*)d_in[1];
    const float* inpb = (const float*)d_in[2];
    const float* ipw  = (const float*)d_in[3];
    const float* cw   = (const float*)d_in[4];
    const float* cb   = (const float*)d_in[5];
    const float* dtb  = (const float*)d_in[6];
    const float* alog = (const float*)d_in[7];
    const float* Dp   = (const float*)d_in[8];
    const float* rmsw = (const float*)d_in[9];
    const float* opw  = (const float*)d_in[10];
    const float* lnw  = (const float*)d_in[11];
    const float* lnb  = (const float*)d_in[12];
    const float* dirw = (const float*)d_in[13];
    const float* dirb = (const float*)d_in[14];
    const float* regw = (const float*)d_in[15];
    const float* regb = (const float*)d_in[16];
    float* out = (float*)d_out;

    void *ph_, *pzx_, *py_;
    cudaGetSymbolAddress(&ph_,  g_h);
    cudaGetSymbolAddress(&pzx_, g_zx);
    cudaGetSymbolAddress(&py_,  g_y);
    float* ph  = (float*)ph_;
    float* pzx = (float*)pzx_;
    float* py  = (float*)py_;

    // h = x @ inp_w + inp_b            [32768 x 256, K=46]  (fp32, tiny)
    sgemm_k<<<dim3(D_MODEL / 64, BL / 64), 128>>>(x, inpw, inpb, ph, BL, D_MODEL, NF, 0);

    const int convdt_threads = BL * (CONV_DIM / 4) + BL * NHEADS;

    for (int i = 0; i < N_LAYERS; i++) {
        // zxbcdt = h @ in_proj_w       [32768 x 1160, K=256]  (tf32 tensor)
        tf32gemm_k<<<dim3((D_IN_PROJ + 63) / 64, BL / 128), 256>>>(
            ph, ipw + (size_t)i * D_MODEL * D_IN_PROJ, pzx,
            BL, D_IN_PROJ, D_MODEL, 0);
        // conv + silu over xBC, fused with (dtA, dt) precompute
        convdt_k<<<(convdt_threads + 255) / 256, 256>>>(
            cw + (size_t)i * CONV_DIM * 4, cb + (size_t)i * CONV_DIM,
            dtb + i * NHEADS, alog + i * NHEADS);
        // chunked SSD scan (+ D*x skip), tensor cores tf32x3
        scan_k<<<NB * NHEADS, 128>>>(Dp + i * NHEADS);
        // y = rmsnorm(y * silu(z)) * rms_w
        gate_rms_k<<<BL, 128>>>(rmsw + (size_t)i * D_INNER);
        // h += y @ out_proj_w          [32768 x 256, K=512]  (tf32 tensor, accumulate)
        tf32gemm_k<<<dim3(D_MODEL / 64, BL / 128), 256>>>(
            py, opw + (size_t)i * D_INNER * D_MODEL, ph,
            BL, D_MODEL, D_INNER, 1);
    }

    ln_part_k<<<dim3(NB, 32), 256>>>();
    final_k<<<1, 256>>>(lnw, lnb, dirw, dirb, regw, regb, out);
}